// round 12
// baseline (speedup 1.0000x reference)
#include <cuda_runtime.h>
#include <cuda_bf16.h>
#include <cstdint>
#include <math.h>

#define KD 4096
#define KI 11008
#define KM 8192

#if !defined(__CUDA_ARCH__) || defined(__CUDA_ARCH_FEAT_SM103_ALL)
#define TC_OK 1
#else
#define TC_OK 0
#endif

// ---------------- persistent scratch (__device__ globals; no allocs) -------
__device__ signed char   g_w8g[(size_t)KI * KD];  // gate w int8 [I,D]
__device__ signed char   g_w8u[(size_t)KI * KD];  // up   w int8 [I,D]
__device__ signed char   g_w8d[(size_t)KD * KI];  // down w int8 [D,I]
__device__ __nv_bfloat16 g_xh[(size_t)KM * KD];   // x hi
__device__ __nv_bfloat16 g_xl[(size_t)KM * KD];   // x lo
__device__ __nv_bfloat16 g_hh[(size_t)KM * KI];   // h hi
__device__ __nv_bfloat16 g_hl[(size_t)KM * KI];   // h lo

// ---------------- PTX helpers ----------------------------------------------
__device__ __forceinline__ uint32_t smem_u32(const void* p) {
    return (uint32_t)__cvta_generic_to_shared(p);
}
__device__ __forceinline__ void cp16(uint32_t dst, const void* src) {
    asm volatile("cp.async.cg.shared.global [%0], [%1], 16;" :: "r"(dst), "l"(src));
}

#if TC_OK
__device__ __forceinline__ uint32_t ctarank() {
    uint32_t r; asm("mov.u32 %0, %%cluster_ctarank;" : "=r"(r)); return r;
}

#define CP_MBAR_ARRIVE(mb) \
    asm volatile("cp.async.mbarrier.arrive.noinc.shared::cta.b64 [%0];" :: "r"(mb) : "memory")
#define MBAR_ARRIVE(mb) \
    asm volatile("mbarrier.arrive.release.cta.shared::cta.b64 _, [%0];" :: "r"(mb) : "memory")

#define TC_ALLOC2(sa, n)  asm volatile("tcgen05.alloc.cta_group::2.sync.aligned.shared::cta.b32 [%0], %1;" :: "r"(sa), "r"(n) : "memory")
#define TC_DEALLOC2(t, n) asm volatile("tcgen05.dealloc.cta_group::2.sync.aligned.b32 %0, %1;" :: "r"(t), "r"(n))
#define TC_RELINQ2()      asm volatile("tcgen05.relinquish_alloc_permit.cta_group::2.sync.aligned;")
#define TC_COMMIT_MC2(mb, mask) asm volatile("tcgen05.commit.cta_group::2.mbarrier::arrive::one.shared::cluster.multicast::cluster.b64 [%0], %1;" :: "r"(mb), "h"((uint16_t)(mask)) : "memory")
#define TC_WAIT_LD()      asm volatile("tcgen05.wait::ld.sync.aligned;" ::: "memory")
#define TC_FENCE_AFTER()  asm volatile("tcgen05.fence::after_thread_sync;" ::: "memory")
#define TC_FENCE_BEFORE() asm volatile("tcgen05.fence::before_thread_sync;" ::: "memory")
#define FENCE_ASYNC()     asm volatile("fence.proxy.async.shared::cta;" ::: "memory")
#define MBAR_INIT(a, c)   asm volatile("mbarrier.init.shared.b64 [%0], %1;" :: "r"(a), "r"(c) : "memory")
#define CLUSTER_SYNC() do { \
    asm volatile("barrier.cluster.arrive.aligned;" ::: "memory"); \
    asm volatile("barrier.cluster.wait.aligned;"   ::: "memory"); } while (0)

__device__ __forceinline__ void mbar_arrive_cluster(uint32_t addr, uint32_t rank) {
    asm volatile("{\n\t.reg .b32 ra;\n\tmapa.shared::cluster.u32 ra, %0, %1;\n\t"
                 "mbarrier.arrive.shared::cluster.b64 _, [ra];\n\t}"
                 :: "r"(addr), "r"(rank) : "memory");
}

#define MBAR_WAIT(mb, ph) do {                                                    \
    uint32_t _m = (mb), _p = (uint32_t)(ph), _d;                                  \
    asm volatile("{\n\t.reg .pred p;\n\t"                                         \
        "mbarrier.try_wait.parity.acquire.cta.shared::cta.b64 p, [%1], %2;\n\t"   \
        "selp.b32 %0, 1, 0, p;\n\t}" : "=r"(_d) : "r"(_m), "r"(_p) : "memory");   \
    if (!_d) {                                                                    \
        asm volatile("{\n\t.reg .pred P1;\n\tWL_%=:\n\t"                          \
            "mbarrier.try_wait.parity.acquire.cta.shared::cta.b64 P1, [%0], %1, 0x989680;\n\t" \
            "@P1 bra.uni WD_%=;\n\tbra.uni WL_%=;\n\tWD_%=:\n\t}"                 \
            :: "r"(_m), "r"(_p) : "memory");                                      \
    }                                                                             \
} while (0)

#define MBAR_WAIT_CL(mb, ph) do {                                                 \
    uint32_t _m = (mb), _p = (uint32_t)(ph), _d;                                  \
    asm volatile("{\n\t.reg .pred p;\n\t"                                         \
        "mbarrier.try_wait.parity.acquire.cluster.shared::cta.b64 p, [%1], %2;\n\t" \
        "selp.b32 %0, 1, 0, p;\n\t}" : "=r"(_d) : "r"(_m), "r"(_p) : "memory");   \
    if (!_d) {                                                                    \
        asm volatile("{\n\t.reg .pred P1;\n\tWL_%=:\n\t"                          \
            "mbarrier.try_wait.parity.acquire.cluster.shared::cta.b64 P1, [%0], %1, 0x989680;\n\t" \
            "@P1 bra.uni WD_%=;\n\tbra.uni WL_%=;\n\tWD_%=:\n\t}"                 \
            :: "r"(_m), "r"(_p) : "memory");                                      \
    }                                                                             \
} while (0)

#define LDTM32(r, ta)                                                             \
    asm volatile("tcgen05.ld.sync.aligned.32x32b.x32.b32 "                        \
        "{%0,%1,%2,%3,%4,%5,%6,%7,%8,%9,%10,%11,%12,%13,%14,%15,"                 \
        "%16,%17,%18,%19,%20,%21,%22,%23,%24,%25,%26,%27,%28,%29,%30,%31},[%32];" \
        : "=r"((r)[0]),"=r"((r)[1]),"=r"((r)[2]),"=r"((r)[3]),                    \
          "=r"((r)[4]),"=r"((r)[5]),"=r"((r)[6]),"=r"((r)[7]),                    \
          "=r"((r)[8]),"=r"((r)[9]),"=r"((r)[10]),"=r"((r)[11]),                  \
          "=r"((r)[12]),"=r"((r)[13]),"=r"((r)[14]),"=r"((r)[15]),                \
          "=r"((r)[16]),"=r"((r)[17]),"=r"((r)[18]),"=r"((r)[19]),                \
          "=r"((r)[20]),"=r"((r)[21]),"=r"((r)[22]),"=r"((r)[23]),                \
          "=r"((r)[24]),"=r"((r)[25]),"=r"((r)[26]),"=r"((r)[27]),                \
          "=r"((r)[28]),"=r"((r)[29]),"=r"((r)[30]),"=r"((r)[31])                 \
        : "r"(ta))

__device__ __forceinline__ uint64_t sdesc(uint32_t addr) {
    return 0x4000404000010000ULL | (uint64_t)((addr >> 4) & 0x3FFF);
}

__device__ __forceinline__ void mma2(uint32_t d, uint64_t a, uint64_t b,
                                     uint32_t idesc, bool acc) {
    uint32_t en = acc ? 1u : 0u;
    asm volatile("{\n\t.reg .pred p;\n\tsetp.ne.u32 p, %5, 0;\n\t"
        "tcgen05.mma.cta_group::2.kind::f16 [%0], %1, %2, %3, "
        "{%4,%4,%4,%4,%4,%4,%4,%4}, p;\n\t}"
        :: "r"(d), "l"(a), "l"(b), "r"(idesc), "r"(0u), "r"(en) : "memory");
}

// idesc: F32 accum, BF16 a/b, N=256, M=256 (cg2 pair)
#define IDESC2 ((1u << 4) | (1u << 7) | (1u << 10) | ((256u / 8) << 17) | ((256u / 16) << 24))

// convert 8 int8 -> 8 bf16 and store 16B to smem
__device__ __forceinline__ void cvt8_sts(uint32_t dst, uint2 raw) {
    union { uint2 u; signed char c[8]; } v; v.u = raw;
    uint32_t o[4];
#pragma unroll
    for (int e = 0; e < 4; ++e) {
        __nv_bfloat162 p;
        p.x = __float2bfloat16((float)v.c[2 * e]);
        p.y = __float2bfloat16((float)v.c[2 * e + 1]);
        o[e] = *(uint32_t*)&p;
    }
    asm volatile("st.shared.v4.b32 [%0], {%1,%2,%3,%4};"
                 :: "r"(dst), "r"(o[0]), "r"(o[1]), "r"(o[2]), "r"(o[3]) : "memory");
}
#endif // TC_OK

// ---------------- fused pre-pass: weight int8 repack + x split --------------
__global__ void __launch_bounds__(256) prep(const int* __restrict__ gw,
                                            const int* __restrict__ uw,
                                            const int* __restrict__ dw,
                                            const float* __restrict__ x) {
    const long n4 = (long)KI * KD / 4;
    const long stride = (long)gridDim.x * blockDim.x;
    long i = blockIdx.x * (long)blockDim.x + threadIdx.x;
    for (; i < 3 * n4; i += stride) {
        const int sel = (int)(i / n4);
        const long j = i - (long)sel * n4;
        const int* w = (sel == 0) ? gw : (sel == 1) ? uw : dw;
        signed char* o = (sel == 0) ? g_w8g : (sel == 1) ? g_w8u : g_w8d;
        int4 v = ((const int4*)w)[j];
        char4 c; c.x = (char)v.x; c.y = (char)v.y; c.z = (char)v.z; c.w = (char)v.w;
        ((char4*)o)[j] = c;
    }
    const long x4 = (long)KM * KD / 4;
    i = blockIdx.x * (long)blockDim.x + threadIdx.x;
    for (; i < x4; i += stride) {
        float4 v = ((const float4*)x)[i];
        __nv_bfloat162 h0, h1, l0, l1;
        h0.x = __float2bfloat16(v.x); l0.x = __float2bfloat16(v.x - __bfloat162float(h0.x));
        h0.y = __float2bfloat16(v.y); l0.y = __float2bfloat16(v.y - __bfloat162float(h0.y));
        h1.x = __float2bfloat16(v.z); l1.x = __float2bfloat16(v.z - __bfloat162float(h1.x));
        h1.y = __float2bfloat16(v.w); l1.y = __float2bfloat16(v.w - __bfloat162float(h1.y));
        ((__nv_bfloat162*)g_xh)[2 * i] = h0; ((__nv_bfloat162*)g_xh)[2 * i + 1] = h1;
        ((__nv_bfloat162*)g_xl)[2 * i] = l0; ((__nv_bfloat162*)g_xl)[2 * i + 1] = l1;
    }
}

// ---------------- persistent GEMMs ------------------------------------------
#define NPAIR    74
#define NTHR     288                    // warps 0-3 epi, 4-7 producers, 8 ctrl

// k1: N=256 tile (gate 256 + up 256 TMEM cols), K-chunk 64, 3 stages x 64KB
#define K1_SST   65536
#define K1_NSTG  3
#define K1_SMEM  (K1_NSTG * K1_SST + 1024)
#define K1_NC    (KD / 64)              // 64
#define K1_NT    (KI / 256)             // 43
#define K1_GM    16
#define K1_TILES (K1_NT * (KM / 256))   // 1376

// k2: N=256 tile, TMEM double-buffered, K-chunk 64, 4 stages x 48KB
#define K2_SST   49152
#define K2_NSTG  4
#define K2_SMEM  (K2_NSTG * K2_SST + 1024)
#define K2_NC    (KI / 64)              // 172
#define K2_NT    (KD / 256)             // 16
#define K2_GM    8
#define K2_TILES (K2_NT * (KM / 256))   // 512

extern __shared__ char dsm[];

// ---------------- K1: fused gate+up, persistent ------------------------------
__global__ void __launch_bounds__(NTHR, 1) __cluster_dims__(2, 1, 1)
k1(const float* __restrict__ gs_p, const float* __restrict__ us_p)
{
#if TC_OK
    const int t = threadIdx.x, wid = t >> 5, lane = t & 31;
    const uint32_t rank = ctarank();
    const int pair = blockIdx.y;
    const uint32_t sb = (smem_u32(dsm) + 1023u) & ~1023u;

    __shared__ uint32_t s_tm[1];
    __shared__ alignas(8) uint64_t s_mb[11];  // full[3], rdy[3], done[3], tdone, epi

    if (wid == 8) TC_ALLOC2(smem_u32(s_tm), 512);
    if (t == 0) {
#pragma unroll
        for (int i = 0; i < 3; ++i) {
            MBAR_INIT(smem_u32(&s_mb[i]),     256);   // full: 128 cp + 128 STS
            MBAR_INIT(smem_u32(&s_mb[3 + i]), 2);     // rdy
            MBAR_INIT(smem_u32(&s_mb[6 + i]), 1);     // done
        }
        MBAR_INIT(smem_u32(&s_mb[9]),  1);            // tdone
        MBAR_INIT(smem_u32(&s_mb[10]), 2);            // epi
    }
    __syncthreads();
    CLUSTER_SYNC();
    uint32_t tm;
    asm volatile("ld.shared.b32 %0, [%1];" : "=r"(tm) : "r"(smem_u32(s_tm)));
    const uint32_t full0 = smem_u32(&s_mb[0]), rdy0 = smem_u32(&s_mb[3]);
    const uint32_t done0 = smem_u32(&s_mb[6]);
    const uint32_t tdone = smem_u32(&s_mb[9]), epib = smem_u32(&s_mb[10]);

    if (t >= 128 && t < 256) {
        // ---------------- producers ----------------
        const int tp  = t - 128;
        const int c16 = tp & 7;
        const int r0  = tp >> 3;                       // 0..15
        const uint32_t swc = (uint32_t)((c16 ^ (r0 & 7)) * 16);
        long q = 0;
        for (int idx = pair; idx < K1_TILES; idx += NPAIR) {
            const int band = idx / (K1_NT * K1_GM);
            const int rsub = idx % (K1_NT * K1_GM);
            const int n0   = (rsub / K1_GM) * 256;
            const int mp   = band * K1_GM + rsub % K1_GM;
            const int m0   = (mp * 2 + (int)rank) * 128;
            const __nv_bfloat16* pxh = g_xh + (size_t)(m0 + r0) * KD + c16 * 8;
            const __nv_bfloat16* pxl = g_xl + (size_t)(m0 + r0) * KD + c16 * 8;
            const signed char*   pg8 = g_w8g + (size_t)(n0 + rank * 128 + r0) * KD + c16 * 8;
            const signed char*   pu8 = g_w8u + (size_t)(n0 + rank * 128 + r0) * KD + c16 * 8;
            for (int c = 0; c < K1_NC; ++c, ++q) {
                const int s = (int)(q % 3);
                if (q >= 3) MBAR_WAIT(done0 + s * 8, (int)((q / 3 - 1) & 1));
                const int k0 = c * 64;
                const uint32_t st = sb + s * K1_SST;
                // B int8 loads first (MLP), then A cp.async, then convert+STS
                uint2 rg[8], ru[8];
#pragma unroll
                for (int i = 0; i < 8; ++i) {
                    const size_t go = (size_t)(16 * i) * KD + k0;
                    rg[i] = *(const uint2*)(pg8 + go);
                    ru[i] = *(const uint2*)(pu8 + go);
                }
#pragma unroll
                for (int i = 0; i < 8; ++i) {
                    const uint32_t d = (uint32_t)((r0 + 16 * i) * 128) + swc;
                    const size_t go = (size_t)(16 * i) * KD + k0;
                    cp16(st + d,         pxh + go);
                    cp16(st + 16384 + d, pxl + go);
                }
#pragma unroll
                for (int i = 0; i < 8; ++i) {
                    const uint32_t d = (uint32_t)((r0 + 16 * i) * 128) + swc;
                    cvt8_sts(st + 32768 + d, rg[i]);
                    cvt8_sts(st + 49152 + d, ru[i]);
                }
                CP_MBAR_ARRIVE(full0 + s * 8);
                MBAR_ARRIVE(full0 + s * 8);
            }
        }
    } else if (t == 257) {
        // ---------------- relay ----------------
        long q = 0;
        for (int idx = pair; idx < K1_TILES; idx += NPAIR)
            for (int c = 0; c < K1_NC; ++c, ++q) {
                const int s = (int)(q % 3);
                MBAR_WAIT(full0 + s * 8, (int)((q / 3) & 1));
                FENCE_ASYNC();
                mbar_arrive_cluster(rdy0 + s * 8, 0);
            }
    } else if (rank == 0 && t == 256) {
        // ---------------- MMA leader ----------------
        long q = 0; int it = 0;
        for (int idx = pair; idx < K1_TILES; idx += NPAIR, ++it) {
            if (it > 0) MBAR_WAIT_CL(epib, (it - 1) & 1);
            for (int c = 0; c < K1_NC; ++c, ++q) {
                const int s = (int)(q % 3);
                MBAR_WAIT_CL(rdy0 + s * 8, (int)((q / 3) & 1));
                const uint32_t st = sb + s * K1_SST;
                const uint64_t da = sdesc(st), dl = sdesc(st + 16384);
                const uint64_t dg = sdesc(st + 32768), du = sdesc(st + 49152);
#pragma unroll
                for (int k = 0; k < 4; ++k) {
                    const bool acc = (c > 0) || (k > 0);
                    mma2(tm,       da + 2 * k, dg + 2 * k, IDESC2, acc);
                    mma2(tm + 256, da + 2 * k, du + 2 * k, IDESC2, acc);
                }
#pragma unroll
                for (int k = 0; k < 4; ++k) {
                    mma2(tm,       dl + 2 * k, dg + 2 * k, IDESC2, true);
                    mma2(tm + 256, dl + 2 * k, du + 2 * k, IDESC2, true);
                }
                TC_COMMIT_MC2(done0 + s * 8, 0x3);
                if (c == K1_NC - 1) TC_COMMIT_MC2(tdone, 0x3);
            }
        }
    } else if (t < 128) {
        // ---------------- consumers (epilogue) ----------------
        const float gsc = gs_p[0], usc = us_p[0];
        int it = 0;
        for (int idx = pair; idx < K1_TILES; idx += NPAIR, ++it) {
            const int band = idx / (K1_NT * K1_GM);
            const int rsub = idx % (K1_NT * K1_GM);
            const int n0   = (rsub / K1_GM) * 256;
            const int mp   = band * K1_GM + rsub % K1_GM;
            const int m0   = (mp * 2 + (int)rank) * 128;
            MBAR_WAIT(tdone, it & 1);
            TC_FENCE_AFTER();
            const int m = m0 + wid * 32 + lane;
#pragma unroll 1
            for (int cb = 0; cb < 8; ++cb) {
                uint32_t rg[32], ru[32];
                LDTM32(rg, tm + cb * 32);
                LDTM32(ru, tm + 256 + cb * 32);
                TC_WAIT_LD();
                alignas(16) ushort oh[32], ol[32];
#pragma unroll
                for (int j = 0; j < 32; ++j) {
                    const float g = __uint_as_float(rg[j]) * gsc;
                    const float u = __uint_as_float(ru[j]) * usc;
                    const float v = (g / (1.0f + __expf(-g))) * u;
                    const __nv_bfloat16 hh = __float2bfloat16(v);
                    const __nv_bfloat16 hl = __float2bfloat16(v - __bfloat162float(hh));
                    oh[j] = *(const ushort*)&hh;
                    ol[j] = *(const ushort*)&hl;
                }
                const size_t off = ((size_t)m * KI + n0 + cb * 32) * 2;
#pragma unroll
                for (int qq = 0; qq < 4; ++qq) {
                    *(uint4*)((char*)g_hh + off + qq * 16) = *(uint4*)&oh[qq * 8];
                    *(uint4*)((char*)g_hl + off + qq * 16) = *(uint4*)&ol[qq * 8];
                }
            }
            TC_FENCE_BEFORE();
            asm volatile("bar.sync 1, 128;" ::: "memory");
            if (t == 0) mbar_arrive_cluster(epib, 0);
        }
    }
    __syncthreads();
    if (wid == 8) { TC_RELINQ2(); TC_DEALLOC2(tm, 512); }
    CLUSTER_SYNC();

#else  // SIMT fallback (compile-only; never runs on GB300)
    const int t = threadIdx.x;
    const float gsc = gs_p[0], usc = us_p[0];
    for (int idx = blockIdx.y; idx < K1_TILES; idx += NPAIR) {
        const int band = idx / (K1_NT * K1_GM);
        const int rsub = idx % (K1_NT * K1_GM);
        const int n0   = (rsub / K1_GM) * 256;
        const int mp   = band * K1_GM + rsub % K1_GM;
        const int m0   = (mp * 2 + blockIdx.x) * 128;
        for (int e = t; e < 128 * 256; e += blockDim.x) {
            const int r = e >> 8, col = e & 255;
            const int m = m0 + r;
            float ag = 0.f, au = 0.f;
            for (int k = 0; k < KD; ++k) {
                const float xv = __bfloat162float(g_xh[(size_t)m * KD + k])
                               + __bfloat162float(g_xl[(size_t)m * KD + k]);
                ag += xv * (float)g_w8g[(size_t)(n0 + col) * KD + k];
                au += xv * (float)g_w8u[(size_t)(n0 + col) * KD + k];
            }
            const float g = ag * gsc;
            const float v = (g / (1.0f + __expf(-g))) * (au * usc);
            const __nv_bfloat16 hh = __float2bfloat16(v);
            const __nv_bfloat16 hl = __float2bfloat16(v - __bfloat162float(hh));
            g_hh[(size_t)m * KI + n0 + col] = hh;
            g_hl[(size_t)m * KI + n0 + col] = hl;
        }
    }
#endif
}

// ---------------- K2: down GEMM, persistent, TMEM double-buffered ------------
__global__ void __launch_bounds__(NTHR, 1) __cluster_dims__(2, 1, 1)
k2(const float* __restrict__ ds_p, float* __restrict__ out)
{
#if TC_OK
    const int t = threadIdx.x, wid = t >> 5, lane = t & 31;
    const uint32_t rank = ctarank();
    const int pair = blockIdx.y;
    const uint32_t sb = (smem_u32(dsm) + 1023u) & ~1023u;

    __shared__ uint32_t s_tm[1];
    __shared__ alignas(8) uint64_t s_mb[16];  // full[4], rdy[4], done[4], tdone[2], epi[2]

    if (wid == 8) TC_ALLOC2(smem_u32(s_tm), 512);
    if (t == 0) {
#pragma unroll
        for (int i = 0; i < 4; ++i) {
            MBAR_INIT(smem_u32(&s_mb[i]),     256);   // full: 128 cp + 128 STS
            MBAR_INIT(smem_u32(&s_mb[4 + i]), 2);     // rdy
            MBAR_INIT(smem_u32(&s_mb[8 + i]), 1);     // done
        }
        MBAR_INIT(smem_u32(&s_mb[12]), 1);            // tdone[0]
        MBAR_INIT(smem_u32(&s_mb[13]), 1);            // tdone[1]
        MBAR_INIT(smem_u32(&s_mb[14]), 2);            // epi[0]
        MBAR_INIT(smem_u32(&s_mb[15]), 2);            // epi[1]
    }
    __syncthreads();
    CLUSTER_SYNC();
    uint32_t tm;
    asm volatile("ld.shared.b32 %0, [%1];" : "=r"(tm) : "r"(smem_u32(s_tm)));
    const uint32_t full0 = smem_u32(&s_mb[0]), rdy0 = smem_u32(&s_mb[4]);
    const uint32_t done0 = smem_u32(&s_mb[8]);
    const uint32_t tdon0 = smem_u32(&s_mb[12]), epi0 = smem_u32(&s_mb[14]);

    if (t >= 128 && t < 256) {
        // ---------------- producers ----------------
        const int tp  = t - 128;
        const int c16 = tp & 7;
        const int r0  = tp >> 3;
        const uint32_t swc = (uint32_t)((c16 ^ (r0 & 7)) * 16);
        long q = 0;
        for (int idx = pair; idx < K2_TILES; idx += NPAIR) {
            const int band = idx / (K2_NT * K2_GM);
            const int rsub = idx % (K2_NT * K2_GM);
            const int n0   = (rsub / K2_GM) * 256;
            const int mp   = band * K2_GM + rsub % K2_GM;
            const int m0   = (mp * 2 + (int)rank) * 128;
            const __nv_bfloat16* pah = g_hh + (size_t)(m0 + r0) * KI + c16 * 8;
            const __nv_bfloat16* pal = g_hl + (size_t)(m0 + r0) * KI + c16 * 8;
            const signed char*   pd8 = g_w8d + (size_t)(n0 + rank * 128 + r0) * KI + c16 * 8;
            for (int c = 0; c < K2_NC; ++c, ++q) {
                const int s = (int)(q % 4);
                if (q >= 4) MBAR_WAIT(done0 + s * 8, (int)((q / 4 - 1) & 1));
                const int k0 = c * 64;
                const uint32_t st = sb + s * K2_SST;
                uint2 rd[8];
#pragma unroll
                for (int i = 0; i < 8; ++i)
                    rd[i] = *(const uint2*)(pd8 + (size_t)(16 * i) * KI + k0);
#pragma unroll
                for (int i = 0; i < 8; ++i) {
                    const uint32_t d = (uint32_t)((r0 + 16 * i) * 128) + swc;
                    const size_t go = (size_t)(16 * i) * KI + k0;
                    cp16(st + d,         pah + go);
                    cp16(st + 16384 + d, pal + go);
                }
#pragma unroll
                for (int i = 0; i < 8; ++i) {
                    const uint32_t d = (uint32_t)((r0 + 16 * i) * 128) + swc;
                    cvt8_sts(st + 32768 + d, rd[i]);
                }
                CP_MBAR_ARRIVE(full0 + s * 8);
                MBAR_ARRIVE(full0 + s * 8);
            }
        }
    } else if (t == 257) {
        // ---------------- relay ----------------
        long q = 0;
        for (int idx = pair; idx < K2_TILES; idx += NPAIR)
            for (int c = 0; c < K2_NC; ++c, ++q) {
                const int s = (int)(q % 4);
                MBAR_WAIT(full0 + s * 8, (int)((q / 4) & 1));
                FENCE_ASYNC();
                mbar_arrive_cluster(rdy0 + s * 8, 0);
            }
    } else if (rank == 0 && t == 256) {
        // ---------------- MMA leader ----------------
        long q = 0; int it = 0;
        for (int idx = pair; idx < K2_TILES; idx += NPAIR, ++it) {
            const int b = it & 1;
            if (it >= 2) MBAR_WAIT_CL(epi0 + b * 8, (it / 2 - 1) & 1);
            for (int c = 0; c < K2_NC; ++c, ++q) {
                const int s = (int)(q % 4);
                MBAR_WAIT_CL(rdy0 + s * 8, (int)((q / 4) & 1));
                const uint32_t st = sb + s * K2_SST;
                const uint64_t da = sdesc(st), dl = sdesc(st + 16384);
                const uint64_t db = sdesc(st + 32768);
                const uint32_t tb = tm + b * 256;
#pragma unroll
                for (int k = 0; k < 4; ++k)
                    mma2(tb, da + 2 * k, db + 2 * k, IDESC2, (c > 0) || (k > 0));
#pragma unroll
                for (int k = 0; k < 4; ++k)
                    mma2(tb, dl + 2 * k, db + 2 * k, IDESC2, true);
                TC_COMMIT_MC2(done0 + s * 8, 0x3);
                if (c == K2_NC - 1) TC_COMMIT_MC2(tdon0 + b * 8, 0x3);
            }
        }
    } else if (t < 128) {
        // ---------------- consumers (epilogue) ----------------
        const float dsc = ds_p[0];
        int it = 0;
        for (int idx = pair; idx < K2_TILES; idx += NPAIR, ++it) {
            const int band = idx / (K2_NT * K2_GM);
            const int rsub = idx % (K2_NT * K2_GM);
            const int n0   = (rsub / K2_GM) * 256;
            const int mp   = band * K2_GM + rsub % K2_GM;
            const int m0   = (mp * 2 + (int)rank) * 128;
            const int b    = it & 1;
            MBAR_WAIT(tdon0 + b * 8, (it / 2) & 1);
            TC_FENCE_AFTER();
            const int m = m0 + wid * 32 + lane;
#pragma unroll 1
            for (int cb = 0; cb < 8; ++cb) {
                uint32_t r[32];
                LDTM32(r, tm + b * 256 + cb * 32);
                TC_WAIT_LD();
                float* p = out + (size_t)m * KD + n0 + cb * 32;
#pragma unroll
                for (int qq = 0; qq < 8; ++qq) {
                    float4 v;
                    v.x = __uint_as_float(r[qq * 4 + 0]) * dsc;
                    v.y = __uint_as_float(r[qq * 4 + 1]) * dsc;
                    v.z = __uint_as_float(r[qq * 4 + 2]) * dsc;
                    v.w = __uint_as_float(r[qq * 4 + 3]) * dsc;
                    *(float4*)(p + qq * 4) = v;
                }
            }
            TC_FENCE_BEFORE();
            asm volatile("bar.sync 1, 128;" ::: "memory");
            if (t == 0) mbar_arrive_cluster(epi0 + b * 8, 0);
        }
    }
    __syncthreads();
    if (wid == 8) { TC_RELINQ2(); TC_DEALLOC2(tm, 512); }
    CLUSTER_SYNC();

#else  // SIMT fallback (compile-only)
    const int t = threadIdx.x;
    const float dsc = ds_p[0];
    for (int idx = blockIdx.y; idx < K2_TILES; idx += NPAIR) {
        const int band = idx / (K2_NT * K2_GM);
        const int rsub = idx % (K2_NT * K2_GM);
        const int n0   = (rsub / K2_GM) * 256;
        const int mp   = band * K2_GM + rsub % K2_GM;
        const int m0   = (mp * 2 + blockIdx.x) * 128;
        for (int e = t; e < 128 * 256; e += blockDim.x) {
            const int r = e >> 8, col = e & 255;
            const int m = m0 + r;
            float acc = 0.f;
            for (int k = 0; k < KI; ++k) {
                const float hv = __bfloat162float(g_hh[(size_t)m * KI + k])
                               + __bfloat162float(g_hl[(size_t)m * KI + k]);
                acc += hv * (float)g_w8d[(size_t)(n0 + col) * KI + k];
            }
            out[(size_t)m * KD + n0 + col] = acc * dsc;
        }
    }
#endif
}

// ---------------- launch ------------------------------------------------------
extern "C" void kernel_launch(void* const* d_in, const int* in_sizes, int n_in,
                              void* d_out, int out_size)
{
    const float* x  = (const float*)d_in[0];
    const int*   gw = (const int*)  d_in[1];
    const float* gs = (const float*)d_in[2];
    const int*   uw = (const int*)  d_in[3];
    const float* us = (const float*)d_in[4];
    const int*   dw = (const int*)  d_in[5];
    const float* ds = (const float*)d_in[6];
    float* out = (float*)d_out;

    cudaFuncSetAttribute(k1, cudaFuncAttributeMaxDynamicSharedMemorySize, K1_SMEM);
    cudaFuncSetAttribute(k2, cudaFuncAttributeMaxDynamicSharedMemorySize, K2_SMEM);

    prep<<<4096, 256>>>(gw, uw, dw, x);

    k1<<<dim3(2, NPAIR, 1), NTHR, K1_SMEM>>>(gs, us);
    k2<<<dim3(2, NPAIR, 1), NTHR, K2_SMEM>>>(ds, out);
}

// round 13
// speedup vs baseline: 1.3455x; 1.3455x over previous
#include <cuda_runtime.h>
#include <cuda_bf16.h>
#include <cuda_fp8.h>
#include <cstdint>
#include <math.h>

#define KD 4096
#define KI 11008
#define KM 8192

#if !defined(__CUDA_ARCH__) || defined(__CUDA_ARCH_FEAT_SM103_ALL)
#define TC_OK 1
#else
#define TC_OK 0
#endif

// ---------------- persistent scratch (__device__ globals; no allocs) -------
__device__ __nv_bfloat16 g_wg[(size_t)KI * KD];   // gate w bf16 [I,D]
__device__ __nv_bfloat16 g_wu[(size_t)KI * KD];   // up   w bf16 [I,D]
__device__ __nv_bfloat16 g_wd[(size_t)KD * KI];   // down w bf16 [D,I]
__device__ unsigned char g_w8g[(size_t)KI * KD];  // e4m3(gate/64)
__device__ unsigned char g_w8u[(size_t)KI * KD];  // e4m3(up/64)
__device__ unsigned char g_w8d[(size_t)KD * KI];  // e4m3(down/2)
__device__ __nv_bfloat16 g_xh[(size_t)KM * KD];   // x hi bf16
__device__ unsigned char g_x8l[(size_t)KM * KD];  // e4m3((x-xh)*64)
__device__ __nv_bfloat16 g_hh[(size_t)KM * KI];   // h hi bf16
__device__ unsigned char g_h8l[(size_t)KM * KI];  // e4m3((h-hh)*2)

// ---------------- PTX helpers ----------------------------------------------
__device__ __forceinline__ uint32_t smem_u32(const void* p) {
    return (uint32_t)__cvta_generic_to_shared(p);
}
__device__ __forceinline__ void cp16(uint32_t dst, const void* src) {
    asm volatile("cp.async.cg.shared.global [%0], [%1], 16;" :: "r"(dst), "l"(src));
}

#if TC_OK
__device__ __forceinline__ uint32_t ctarank() {
    uint32_t r; asm("mov.u32 %0, %%cluster_ctarank;" : "=r"(r)); return r;
}

#define CP_MBAR_ARRIVE(mb) \
    asm volatile("cp.async.mbarrier.arrive.noinc.shared::cta.b64 [%0];" :: "r"(mb) : "memory")

#define TC_ALLOC2(sa, n)  asm volatile("tcgen05.alloc.cta_group::2.sync.aligned.shared::cta.b32 [%0], %1;" :: "r"(sa), "r"(n) : "memory")
#define TC_DEALLOC2(t, n) asm volatile("tcgen05.dealloc.cta_group::2.sync.aligned.b32 %0, %1;" :: "r"(t), "r"(n))
#define TC_RELINQ2()      asm volatile("tcgen05.relinquish_alloc_permit.cta_group::2.sync.aligned;")
#define TC_COMMIT_MC2(mb, mask) asm volatile("tcgen05.commit.cta_group::2.mbarrier::arrive::one.shared::cluster.multicast::cluster.b64 [%0], %1;" :: "r"(mb), "h"((uint16_t)(mask)) : "memory")
#define TC_WAIT_LD()      asm volatile("tcgen05.wait::ld.sync.aligned;" ::: "memory")
#define TC_FENCE_AFTER()  asm volatile("tcgen05.fence::after_thread_sync;" ::: "memory")
#define TC_FENCE_BEFORE() asm volatile("tcgen05.fence::before_thread_sync;" ::: "memory")
#define FENCE_ASYNC()     asm volatile("fence.proxy.async.shared::cta;" ::: "memory")
#define MBAR_INIT(a, c)   asm volatile("mbarrier.init.shared.b64 [%0], %1;" :: "r"(a), "r"(c) : "memory")
#define CLUSTER_SYNC() do { \
    asm volatile("barrier.cluster.arrive.aligned;" ::: "memory"); \
    asm volatile("barrier.cluster.wait.aligned;"   ::: "memory"); } while (0)

__device__ __forceinline__ void mbar_arrive_cluster(uint32_t addr, uint32_t rank) {
    asm volatile("{\n\t.reg .b32 ra;\n\tmapa.shared::cluster.u32 ra, %0, %1;\n\t"
                 "mbarrier.arrive.shared::cluster.b64 _, [ra];\n\t}"
                 :: "r"(addr), "r"(rank) : "memory");
}

#define MBAR_WAIT(mb, ph) do {                                                    \
    uint32_t _m = (mb), _p = (uint32_t)(ph), _d;                                  \
    asm volatile("{\n\t.reg .pred p;\n\t"                                         \
        "mbarrier.try_wait.parity.acquire.cta.shared::cta.b64 p, [%1], %2;\n\t"   \
        "selp.b32 %0, 1, 0, p;\n\t}" : "=r"(_d) : "r"(_m), "r"(_p) : "memory");   \
    if (!_d) {                                                                    \
        asm volatile("{\n\t.reg .pred P1;\n\tWL_%=:\n\t"                          \
            "mbarrier.try_wait.parity.acquire.cta.shared::cta.b64 P1, [%0], %1, 0x989680;\n\t" \
            "@P1 bra.uni WD_%=;\n\tbra.uni WL_%=;\n\tWD_%=:\n\t}"                 \
            :: "r"(_m), "r"(_p) : "memory");                                      \
    }                                                                             \
} while (0)

#define MBAR_WAIT_CL(mb, ph) do {                                                 \
    uint32_t _m = (mb), _p = (uint32_t)(ph), _d;                                  \
    asm volatile("{\n\t.reg .pred p;\n\t"                                         \
        "mbarrier.try_wait.parity.acquire.cluster.shared::cta.b64 p, [%1], %2;\n\t" \
        "selp.b32 %0, 1, 0, p;\n\t}" : "=r"(_d) : "r"(_m), "r"(_p) : "memory");   \
    if (!_d) {                                                                    \
        asm volatile("{\n\t.reg .pred P1;\n\tWL_%=:\n\t"                          \
            "mbarrier.try_wait.parity.acquire.cluster.shared::cta.b64 P1, [%0], %1, 0x989680;\n\t" \
            "@P1 bra.uni WD_%=;\n\tbra.uni WL_%=;\n\tWD_%=:\n\t}"                 \
            :: "r"(_m), "r"(_p) : "memory");                                      \
    }                                                                             \
} while (0)

#define LDTM32(r, ta)                                                             \
    asm volatile("tcgen05.ld.sync.aligned.32x32b.x32.b32 "                        \
        "{%0,%1,%2,%3,%4,%5,%6,%7,%8,%9,%10,%11,%12,%13,%14,%15,"                 \
        "%16,%17,%18,%19,%20,%21,%22,%23,%24,%25,%26,%27,%28,%29,%30,%31},[%32];" \
        : "=r"((r)[0]),"=r"((r)[1]),"=r"((r)[2]),"=r"((r)[3]),                    \
          "=r"((r)[4]),"=r"((r)[5]),"=r"((r)[6]),"=r"((r)[7]),                    \
          "=r"((r)[8]),"=r"((r)[9]),"=r"((r)[10]),"=r"((r)[11]),                  \
          "=r"((r)[12]),"=r"((r)[13]),"=r"((r)[14]),"=r"((r)[15]),                \
          "=r"((r)[16]),"=r"((r)[17]),"=r"((r)[18]),"=r"((r)[19]),                \
          "=r"((r)[20]),"=r"((r)[21]),"=r"((r)[22]),"=r"((r)[23]),                \
          "=r"((r)[24]),"=r"((r)[25]),"=r"((r)[26]),"=r"((r)[27]),                \
          "=r"((r)[28]),"=r"((r)[29]),"=r"((r)[30]),"=r"((r)[31])                 \
        : "r"(ta))

__device__ __forceinline__ uint64_t sdesc(uint32_t addr) {      // SW128 bf16 tiles
    return 0x4000404000010000ULL | (uint64_t)((addr >> 4) & 0x3FFF);
}
__device__ __forceinline__ uint64_t sdesc64(uint32_t addr) {    // SW64 fp8 tiles
    return (4ull << 61) | (1ull << 46) | (32ull << 32) | (1ull << 16)
         | (uint64_t)((addr >> 4) & 0x3FFF);
}
__device__ __forceinline__ uint32_t sw64(uint32_t o) { return o ^ ((o >> 3) & 0x30); }

__device__ __forceinline__ void mma2(uint32_t d, uint64_t a, uint64_t b,
                                     uint32_t idesc, bool acc) {
    uint32_t en = acc ? 1u : 0u;
    asm volatile("{\n\t.reg .pred p;\n\tsetp.ne.u32 p, %5, 0;\n\t"
        "tcgen05.mma.cta_group::2.kind::f16 [%0], %1, %2, %3, "
        "{%4,%4,%4,%4,%4,%4,%4,%4}, p;\n\t}"
        :: "r"(d), "l"(a), "l"(b), "r"(idesc), "r"(0u), "r"(en) : "memory");
}
__device__ __forceinline__ void mma2_f8(uint32_t d, uint64_t a, uint64_t b,
                                        uint32_t idesc) {
    asm volatile("{\n\t.reg .pred p;\n\tsetp.ne.u32 p, 1, 0;\n\t"
        "tcgen05.mma.cta_group::2.kind::f8f6f4 [%0], %1, %2, %3, "
        "{%4,%4,%4,%4,%4,%4,%4,%4}, p;\n\t}"
        :: "r"(d), "l"(a), "l"(b), "r"(idesc), "r"(0u) : "memory");
}

// bf16: F32 acc, BF16 a/b, N=256, M=256 cg2
#define IDESC2    ((1u << 4) | (1u << 7) | (1u << 10) | ((256u / 8) << 17) | ((256u / 16) << 24))
// fp8:  F32 acc, E4M3 a/b (=0), N=256, M=256 cg2
#define IDESC2_F8 ((1u << 4) | ((256u / 8) << 17) | ((256u / 16) << 24))
#endif // TC_OK

// ---------------- fused pre-pass ---------------------------------------------
__global__ void __launch_bounds__(256) prep(const int* __restrict__ gw,
                                            const int* __restrict__ uw,
                                            const int* __restrict__ dw,
                                            const float* __restrict__ x) {
    const long n4 = (long)KI * KD / 4;
    const long stride = (long)gridDim.x * blockDim.x;
    long i = blockIdx.x * (long)blockDim.x + threadIdx.x;
    for (; i < 3 * n4; i += stride) {
        const int sel = (int)(i / n4);
        const long j = i - (long)sel * n4;
        const int* w = (sel == 0) ? gw : (sel == 1) ? uw : dw;
        __nv_bfloat16* o = (sel == 0) ? g_wg : (sel == 1) ? g_wu : g_wd;
        unsigned char* o8 = (sel == 0) ? g_w8g : (sel == 1) ? g_w8u : g_w8d;
        const float sc8 = (sel == 2) ? 0.5f : (1.0f / 64.0f);
        int4 v = ((const int4*)w)[j];
        __nv_bfloat162 p0, p1;
        p0.x = __float2bfloat16((float)v.x); p0.y = __float2bfloat16((float)v.y);
        p1.x = __float2bfloat16((float)v.z); p1.y = __float2bfloat16((float)v.w);
        ((__nv_bfloat162*)o)[2 * j]     = p0;
        ((__nv_bfloat162*)o)[2 * j + 1] = p1;
        uchar4 c8;
        c8.x = __nv_fp8_e4m3((float)v.x * sc8).__x;
        c8.y = __nv_fp8_e4m3((float)v.y * sc8).__x;
        c8.z = __nv_fp8_e4m3((float)v.z * sc8).__x;
        c8.w = __nv_fp8_e4m3((float)v.w * sc8).__x;
        ((uchar4*)o8)[j] = c8;
    }
    const long x4 = (long)KM * KD / 4;
    i = blockIdx.x * (long)blockDim.x + threadIdx.x;
    for (; i < x4; i += stride) {
        float4 v = ((const float4*)x)[i];
        __nv_bfloat162 h0, h1;
        h0.x = __float2bfloat16(v.x); h0.y = __float2bfloat16(v.y);
        h1.x = __float2bfloat16(v.z); h1.y = __float2bfloat16(v.w);
        ((__nv_bfloat162*)g_xh)[2 * i] = h0; ((__nv_bfloat162*)g_xh)[2 * i + 1] = h1;
        uchar4 l8;
        l8.x = __nv_fp8_e4m3((v.x - __bfloat162float(h0.x)) * 64.0f).__x;
        l8.y = __nv_fp8_e4m3((v.y - __bfloat162float(h0.y)) * 64.0f).__x;
        l8.z = __nv_fp8_e4m3((v.z - __bfloat162float(h1.x)) * 64.0f).__x;
        l8.w = __nv_fp8_e4m3((v.w - __bfloat162float(h1.y)) * 64.0f).__x;
        ((uchar4*)g_x8l)[i] = l8;
    }
}

// ---------------- persistent GEMMs -------------------------------------------
#define NPAIR    74
#define NTHR     288
// stage: [AH 16K][B0 16K][B1 16K][AL8 8K][B0L8 8K][B1L8 8K] = 72 KB
#define SST      73728
#define OF_AH    0
#define OF_B0    16384
#define OF_B1    32768
#define OF_AL    49152
#define OF_B0L   57344
#define OF_B1L   65536
#define GSMEM    (3 * SST + 1024)

#define K1_NC    (KD / 64)
#define K1_NT    (KI / 256)
#define K1_GM    16
#define K1_TILES (K1_NT * (KM / 256))    // 1376
#define K2_NC    (KI / 64)
#define K2_NT    (KD / 512)
#define K2_GM    8
#define K2_TILES (K2_NT * (KM / 256))    // 256

extern __shared__ char dsm[];

// ---------------- K1: fused gate+up, persistent ------------------------------
__global__ void __launch_bounds__(NTHR, 1) __cluster_dims__(2, 1, 1)
k1(const float* __restrict__ gs_p, const float* __restrict__ us_p)
{
#if TC_OK
    const int t = threadIdx.x, wid = t >> 5, lane = t & 31;
    const uint32_t rank = ctarank();
    const int pair = blockIdx.y;
    const uint32_t sb = (smem_u32(dsm) + 1023u) & ~1023u;

    __shared__ uint32_t s_tm[1];
    __shared__ alignas(8) uint64_t s_mb[11];  // full[3], rdy[3], done[3], tdone, epi

    if (wid == 8) TC_ALLOC2(smem_u32(s_tm), 512);
    if (t == 0) {
#pragma unroll
        for (int i = 0; i < 3; ++i) {
            MBAR_INIT(smem_u32(&s_mb[i]),     128);
            MBAR_INIT(smem_u32(&s_mb[3 + i]), 2);
            MBAR_INIT(smem_u32(&s_mb[6 + i]), 1);
        }
        MBAR_INIT(smem_u32(&s_mb[9]),  1);
        MBAR_INIT(smem_u32(&s_mb[10]), 2);
    }
    __syncthreads();
    CLUSTER_SYNC();
    uint32_t tm;
    asm volatile("ld.shared.b32 %0, [%1];" : "=r"(tm) : "r"(smem_u32(s_tm)));
    const uint32_t full0 = smem_u32(&s_mb[0]), rdy0 = smem_u32(&s_mb[3]);
    const uint32_t done0 = smem_u32(&s_mb[6]);
    const uint32_t tdone = smem_u32(&s_mb[9]), epib = smem_u32(&s_mb[10]);

    if (t >= 128 && t < 256) {
        // ---------------- producers ----------------
        const int tp  = t - 128;
        const int c16 = tp & 7;
        const int r0  = tp >> 3;                       // 0..15 (bf16 tiles)
        const uint32_t swc = (uint32_t)((c16 ^ (r0 & 7)) * 16);
        const int c4  = tp & 3;                        // fp8 tiles
        const int r4  = tp >> 2;                       // 0..31
        long q = 0;
        for (int idx = pair; idx < K1_TILES; idx += NPAIR) {
            const int band = idx / (K1_NT * K1_GM);
            const int rsub = idx % (K1_NT * K1_GM);
            const int n0   = (rsub / K1_GM) * 256;
            const int mp   = band * K1_GM + rsub % K1_GM;
            const int m0   = (mp * 2 + (int)rank) * 128;
            const __nv_bfloat16* pxh = g_xh + (size_t)(m0 + r0) * KD + c16 * 8;
            const __nv_bfloat16* pg  = g_wg + (size_t)(n0 + rank * 128 + r0) * KD + c16 * 8;
            const __nv_bfloat16* pu  = g_wu + (size_t)(n0 + rank * 128 + r0) * KD + c16 * 8;
            const unsigned char* pxl = g_x8l + (size_t)(m0 + r4) * KD + c4 * 16;
            const unsigned char* pg8 = g_w8g + (size_t)(n0 + rank * 128 + r4) * KD + c4 * 16;
            const unsigned char* pu8 = g_w8u + (size_t)(n0 + rank * 128 + r4) * KD + c4 * 16;
            for (int c = 0; c < K1_NC; ++c, ++q) {
                const int s = (int)(q % 3);
                if (q >= 3) MBAR_WAIT(done0 + s * 8, (int)((q / 3 - 1) & 1));
                const int k0 = c * 64;                 // elements (bf16) == bytes (fp8)
                const uint32_t st = sb + s * SST;
#pragma unroll
                for (int i = 0; i < 8; ++i) {
                    const uint32_t d = (uint32_t)((r0 + 16 * i) * 128) + swc;
                    const size_t go = (size_t)(16 * i) * KD + k0;
                    cp16(st + OF_AH + d, pxh + go);
                    cp16(st + OF_B0 + d, pg + go);
                    cp16(st + OF_B1 + d, pu + go);
                }
#pragma unroll
                for (int i = 0; i < 4; ++i) {
                    const uint32_t o = (uint32_t)((r4 + 32 * i) * 64 + c4 * 16);
                    const uint32_t d = sw64(o);
                    const size_t go = (size_t)(32 * i) * KD + k0;
                    cp16(st + OF_AL  + d, pxl + go);
                    cp16(st + OF_B0L + d, pg8 + go);
                    cp16(st + OF_B1L + d, pu8 + go);
                }
                CP_MBAR_ARRIVE(full0 + s * 8);
            }
        }
    } else if (t == 257) {
        // ---------------- relay ----------------
        long q = 0;
        for (int idx = pair; idx < K1_TILES; idx += NPAIR)
            for (int c = 0; c < K1_NC; ++c, ++q) {
                const int s = (int)(q % 3);
                MBAR_WAIT(full0 + s * 8, (int)((q / 3) & 1));
                FENCE_ASYNC();
                mbar_arrive_cluster(rdy0 + s * 8, 0);
            }
    } else if (rank == 0 && t == 256) {
        // ---------------- MMA leader ----------------
        long q = 0; int it = 0;
        for (int idx = pair; idx < K1_TILES; idx += NPAIR, ++it) {
            if (it > 0) MBAR_WAIT_CL(epib, (it - 1) & 1);
            for (int c = 0; c < K1_NC; ++c, ++q) {
                const int s = (int)(q % 3);
                MBAR_WAIT_CL(rdy0 + s * 8, (int)((q / 3) & 1));
                const uint32_t st = sb + s * SST;
                const uint64_t da = sdesc(st + OF_AH);
                const uint64_t dg = sdesc(st + OF_B0), du = sdesc(st + OF_B1);
                const uint64_t dal = sdesc64(st + OF_AL);
                const uint64_t dgl = sdesc64(st + OF_B0L), dul = sdesc64(st + OF_B1L);
#pragma unroll
                for (int k = 0; k < 4; ++k) {
                    const bool acc = (c > 0) || (k > 0);
                    mma2(tm,       da + 2 * k, dg + 2 * k, IDESC2, acc);
                    mma2(tm + 256, da + 2 * k, du + 2 * k, IDESC2, acc);
                }
#pragma unroll
                for (int k = 0; k < 2; ++k) {          // fp8: K=32/dispatch
                    mma2_f8(tm,       dal + 2 * k, dgl + 2 * k, IDESC2_F8);
                    mma2_f8(tm + 256, dal + 2 * k, dul + 2 * k, IDESC2_F8);
                }
                TC_COMMIT_MC2(done0 + s * 8, 0x3);
                if (c == K1_NC - 1) TC_COMMIT_MC2(tdone, 0x3);
            }
        }
    } else if (t < 128) {
        // ---------------- consumers (epilogue) ----------------
        const float gsc = gs_p[0], usc = us_p[0];
        int it = 0;
        for (int idx = pair; idx < K1_TILES; idx += NPAIR, ++it) {
            const int band = idx / (K1_NT * K1_GM);
            const int rsub = idx % (K1_NT * K1_GM);
            const int n0   = (rsub / K1_GM) * 256;
            const int mp   = band * K1_GM + rsub % K1_GM;
            const int m0   = (mp * 2 + (int)rank) * 128;
            MBAR_WAIT(tdone, it & 1);
            TC_FENCE_AFTER();
            const int m = m0 + wid * 32 + lane;
#pragma unroll 1
            for (int cb = 0; cb < 8; ++cb) {
                uint32_t rg[32], ru[32];
                LDTM32(rg, tm + cb * 32);
                LDTM32(ru, tm + 256 + cb * 32);
                TC_WAIT_LD();
                alignas(16) ushort oh[32];
                alignas(16) unsigned char ol8[32];
#pragma unroll
                for (int j = 0; j < 32; ++j) {
                    const float g = __uint_as_float(rg[j]) * gsc;
                    const float u = __uint_as_float(ru[j]) * usc;
                    const float v = (g / (1.0f + __expf(-g))) * u;
                    const __nv_bfloat16 hh = __float2bfloat16(v);
                    oh[j] = *(const ushort*)&hh;
                    ol8[j] = __nv_fp8_e4m3((v - __bfloat162float(hh)) * 2.0f).__x;
                }
                const size_t eoff = (size_t)m * KI + n0 + cb * 32;
#pragma unroll
                for (int qq = 0; qq < 4; ++qq)
                    *(uint4*)((char*)g_hh + eoff * 2 + qq * 16) = *(uint4*)&oh[qq * 8];
#pragma unroll
                for (int qq = 0; qq < 2; ++qq)
                    *(uint4*)(g_h8l + eoff + qq * 16) = *(uint4*)&ol8[qq * 16];
            }
            TC_FENCE_BEFORE();
            asm volatile("bar.sync 1, 128;" ::: "memory");
            if (t == 0) mbar_arrive_cluster(epib, 0);
        }
    }
    __syncthreads();
    if (wid == 8) { TC_RELINQ2(); TC_DEALLOC2(tm, 512); }
    CLUSTER_SYNC();

#else  // SIMT fallback (compile-only; never runs on GB300)
    const int t = threadIdx.x;
    const float gsc = gs_p[0], usc = us_p[0];
    for (int idx = blockIdx.y; idx < K1_TILES; idx += NPAIR) {
        const int band = idx / (K1_NT * K1_GM);
        const int rsub = idx % (K1_NT * K1_GM);
        const int n0   = (rsub / K1_GM) * 256;
        const int mp   = band * K1_GM + rsub % K1_GM;
        const int m0   = (mp * 2 + blockIdx.x) * 128;
        for (int e = t; e < 128 * 256; e += blockDim.x) {
            const int r = e >> 8, col = e & 255;
            const int m = m0 + r;
            float ag = 0.f, au = 0.f;
            for (int k = 0; k < KD; ++k) {
                const float xv = __bfloat162float(g_xh[(size_t)m * KD + k]);
                ag += xv * __bfloat162float(g_wg[(size_t)(n0 + col) * KD + k]);
                au += xv * __bfloat162float(g_wu[(size_t)(n0 + col) * KD + k]);
            }
            const float g = ag * gsc;
            const float v = (g / (1.0f + __expf(-g))) * (au * usc);
            const __nv_bfloat16 hh = __float2bfloat16(v);
            g_hh[(size_t)m * KI + n0 + col] = hh;
            g_h8l[(size_t)m * KI + n0 + col] =
                __nv_fp8_e4m3((v - __bfloat162float(hh)) * 2.0f).__x;
        }
    }
#endif
}

// ---------------- K2: down GEMM, persistent -----------------------------------
__global__ void __launch_bounds__(NTHR, 1) __cluster_dims__(2, 1, 1)
k2(const float* __restrict__ ds_p, float* __restrict__ out)
{
#if TC_OK
    const int t = threadIdx.x, wid = t >> 5, lane = t & 31;
    const uint32_t rank = ctarank();
    const int pair = blockIdx.y;
    const uint32_t sb = (smem_u32(dsm) + 1023u) & ~1023u;

    __shared__ uint32_t s_tm[1];
    __shared__ alignas(8) uint64_t s_mb[11];

    if (wid == 8) TC_ALLOC2(smem_u32(s_tm), 512);
    if (t == 0) {
#pragma unroll
        for (int i = 0; i < 3; ++i) {
            MBAR_INIT(smem_u32(&s_mb[i]),     128);
            MBAR_INIT(smem_u32(&s_mb[3 + i]), 2);
            MBAR_INIT(smem_u32(&s_mb[6 + i]), 1);
        }
        MBAR_INIT(smem_u32(&s_mb[9]),  1);
        MBAR_INIT(smem_u32(&s_mb[10]), 2);
    }
    __syncthreads();
    CLUSTER_SYNC();
    uint32_t tm;
    asm volatile("ld.shared.b32 %0, [%1];" : "=r"(tm) : "r"(smem_u32(s_tm)));
    const uint32_t full0 = smem_u32(&s_mb[0]), rdy0 = smem_u32(&s_mb[3]);
    const uint32_t done0 = smem_u32(&s_mb[6]);
    const uint32_t tdone = smem_u32(&s_mb[9]), epib = smem_u32(&s_mb[10]);

    if (t >= 128 && t < 256) {
        // ---------------- producers ----------------
        const int tp  = t - 128;
        const int c16 = tp & 7;
        const int r0  = tp >> 3;
        const uint32_t swc = (uint32_t)((c16 ^ (r0 & 7)) * 16);
        const int c4  = tp & 3;
        const int r4  = tp >> 2;
        long q = 0;
        for (int idx = pair; idx < K2_TILES; idx += NPAIR) {
            const int band = idx / (K2_NT * K2_GM);
            const int rsub = idx % (K2_NT * K2_GM);
            const int n0   = (rsub / K2_GM) * 512;
            const int mp   = band * K2_GM + rsub % K2_GM;
            const int m0   = (mp * 2 + (int)rank) * 128;
            const __nv_bfloat16* pah = g_hh + (size_t)(m0 + r0) * KI + c16 * 8;
            const __nv_bfloat16* pb0 = g_wd + (size_t)(n0 +       rank * 128 + r0) * KI + c16 * 8;
            const __nv_bfloat16* pb1 = g_wd + (size_t)(n0 + 256 + rank * 128 + r0) * KI + c16 * 8;
            const unsigned char* pal = g_h8l + (size_t)(m0 + r4) * KI + c4 * 16;
            const unsigned char* p08 = g_w8d + (size_t)(n0 +       rank * 128 + r4) * KI + c4 * 16;
            const unsigned char* p18 = g_w8d + (size_t)(n0 + 256 + rank * 128 + r4) * KI + c4 * 16;
            for (int c = 0; c < K2_NC; ++c, ++q) {
                const int s = (int)(q % 3);
                if (q >= 3) MBAR_WAIT(done0 + s * 8, (int)((q / 3 - 1) & 1));
                const int k0 = c * 64;
                const uint32_t st = sb + s * SST;
#pragma unroll
                for (int i = 0; i < 8; ++i) {
                    const uint32_t d = (uint32_t)((r0 + 16 * i) * 128) + swc;
                    const size_t go = (size_t)(16 * i) * KI + k0;
                    cp16(st + OF_AH + d, pah + go);
                    cp16(st + OF_B0 + d, pb0 + go);
                    cp16(st + OF_B1 + d, pb1 + go);
                }
#pragma unroll
                for (int i = 0; i < 4; ++i) {
                    const uint32_t o = (uint32_t)((r4 + 32 * i) * 64 + c4 * 16);
                    const uint32_t d = sw64(o);
                    const size_t go = (size_t)(32 * i) * KI + k0;
                    cp16(st + OF_AL  + d, pal + go);
                    cp16(st + OF_B0L + d, p08 + go);
                    cp16(st + OF_B1L + d, p18 + go);
                }
                CP_MBAR_ARRIVE(full0 + s * 8);
            }
        }
    } else if (t == 257) {
        long q = 0;
        for (int idx = pair; idx < K2_TILES; idx += NPAIR)
            for (int c = 0; c < K2_NC; ++c, ++q) {
                const int s = (int)(q % 3);
                MBAR_WAIT(full0 + s * 8, (int)((q / 3) & 1));
                FENCE_ASYNC();
                mbar_arrive_cluster(rdy0 + s * 8, 0);
            }
    } else if (rank == 0 && t == 256) {
        long q = 0; int it = 0;
        for (int idx = pair; idx < K2_TILES; idx += NPAIR, ++it) {
            if (it > 0) MBAR_WAIT_CL(epib, (it - 1) & 1);
            for (int c = 0; c < K2_NC; ++c, ++q) {
                const int s = (int)(q % 3);
                MBAR_WAIT_CL(rdy0 + s * 8, (int)((q / 3) & 1));
                const uint32_t st = sb + s * SST;
                const uint64_t da = sdesc(st + OF_AH);
                const uint64_t d0 = sdesc(st + OF_B0), d1 = sdesc(st + OF_B1);
                const uint64_t dal = sdesc64(st + OF_AL);
                const uint64_t d0l = sdesc64(st + OF_B0L), d1l = sdesc64(st + OF_B1L);
#pragma unroll
                for (int k = 0; k < 4; ++k) {
                    const bool acc = (c > 0) || (k > 0);
                    mma2(tm,       da + 2 * k, d0 + 2 * k, IDESC2, acc);
                    mma2(tm + 256, da + 2 * k, d1 + 2 * k, IDESC2, acc);
                }
#pragma unroll
                for (int k = 0; k < 2; ++k) {
                    mma2_f8(tm,       dal + 2 * k, d0l + 2 * k, IDESC2_F8);
                    mma2_f8(tm + 256, dal + 2 * k, d1l + 2 * k, IDESC2_F8);
                }
                TC_COMMIT_MC2(done0 + s * 8, 0x3);
                if (c == K2_NC - 1) TC_COMMIT_MC2(tdone, 0x3);
            }
        }
    } else if (t < 128) {
        const float dsc = ds_p[0];
        int it = 0;
        for (int idx = pair; idx < K2_TILES; idx += NPAIR, ++it) {
            const int band = idx / (K2_NT * K2_GM);
            const int rsub = idx % (K2_NT * K2_GM);
            const int n0   = (rsub / K2_GM) * 512;
            const int mp   = band * K2_GM + rsub % K2_GM;
            const int m0   = (mp * 2 + (int)rank) * 128;
            MBAR_WAIT(tdone, it & 1);
            TC_FENCE_AFTER();
            const int m = m0 + wid * 32 + lane;
#pragma unroll 1
            for (int cb = 0; cb < 16; ++cb) {
                uint32_t r[32];
                LDTM32(r, tm + cb * 32);
                TC_WAIT_LD();
                float* p = out + (size_t)m * KD + n0 + cb * 32;
#pragma unroll
                for (int qq = 0; qq < 8; ++qq) {
                    float4 v;
                    v.x = __uint_as_float(r[qq * 4 + 0]) * dsc;
                    v.y = __uint_as_float(r[qq * 4 + 1]) * dsc;
                    v.z = __uint_as_float(r[qq * 4 + 2]) * dsc;
                    v.w = __uint_as_float(r[qq * 4 + 3]) * dsc;
                    *(float4*)(p + qq * 4) = v;
                }
            }
            TC_FENCE_BEFORE();
            asm volatile("bar.sync 1, 128;" ::: "memory");
            if (t == 0) mbar_arrive_cluster(epib, 0);
        }
    }
    __syncthreads();
    if (wid == 8) { TC_RELINQ2(); TC_DEALLOC2(tm, 512); }
    CLUSTER_SYNC();

#else  // SIMT fallback (compile-only)
    const int t = threadIdx.x;
    const float dsc = ds_p[0];
    for (int idx = blockIdx.y; idx < K2_TILES; idx += NPAIR) {
        const int band = idx / (K2_NT * K2_GM);
        const int rsub = idx % (K2_NT * K2_GM);
        const int n0   = (rsub / K2_GM) * 512;
        const int mp   = band * K2_GM + rsub % K2_GM;
        const int m0   = (mp * 2 + blockIdx.x) * 128;
        for (int e = t; e < 128 * 512; e += blockDim.x) {
            const int r = e >> 9, col = e & 511;
            const int m = m0 + r;
            float acc = 0.f;
            for (int k = 0; k < KI; ++k)
                acc += __bfloat162float(g_hh[(size_t)m * KI + k])
                     * __bfloat162float(g_wd[(size_t)(n0 + col) * KI + k]);
            out[(size_t)m * KD + n0 + col] = acc * dsc;
        }
    }
#endif
}

// ---------------- launch ------------------------------------------------------
extern "C" void kernel_launch(void* const* d_in, const int* in_sizes, int n_in,
                              void* d_out, int out_size)
{
    const float* x  = (const float*)d_in[0];
    const int*   gw = (const int*)  d_in[1];
    const float* gs = (const float*)d_in[2];
    const int*   uw = (const int*)  d_in[3];
    const float* us = (const float*)d_in[4];
    const int*   dw = (const int*)  d_in[5];
    const float* ds = (const float*)d_in[6];
    float* out = (float*)d_out;

    cudaFuncSetAttribute(k1, cudaFuncAttributeMaxDynamicSharedMemorySize, GSMEM);
    cudaFuncSetAttribute(k2, cudaFuncAttributeMaxDynamicSharedMemorySize, GSMEM);

    prep<<<4096, 256>>>(gw, uw, dw, x);

    k1<<<dim3(2, NPAIR, 1), NTHR, GSMEM>>>(gs, us);
    k2<<<dim3(2, NPAIR, 1), NTHR, GSMEM>>>(ds, out);
}

// round 14
// speedup vs baseline: 1.3760x; 1.0227x over previous
#include <cuda_runtime.h>
#include <cuda_bf16.h>
#include <cuda_fp8.h>
#include <cstdint>
#include <math.h>

#define KD 4096
#define KI 11008
#define KM 8192

#if !defined(__CUDA_ARCH__) || defined(__CUDA_ARCH_FEAT_SM103_ALL)
#define TC_OK 1
#else
#define TC_OK 0
#endif

// ---------------- persistent scratch (__device__ globals; no allocs) -------
__device__ __nv_bfloat16 g_wg[(size_t)KI * KD];   // gate w bf16 [I,D]
__device__ __nv_bfloat16 g_wu[(size_t)KI * KD];   // up   w bf16 [I,D]
__device__ __nv_bfloat16 g_wd[(size_t)KD * KI];   // down w bf16 [D,I]
__device__ unsigned char g_w8g[(size_t)KI * KD];  // e4m3(gate/64)
__device__ unsigned char g_w8u[(size_t)KI * KD];  // e4m3(up/64)
__device__ unsigned char g_w8d[(size_t)KD * KI];  // e4m3(down/2)
__device__ __nv_bfloat16 g_xh[(size_t)KM * KD];   // x hi bf16
__device__ unsigned char g_x8l[(size_t)KM * KD];  // e4m3((x-xh)*64)
__device__ __nv_bfloat16 g_hh[(size_t)KM * KI];   // h hi bf16
__device__ unsigned char g_h8l[(size_t)KM * KI];  // e4m3((h-hh)*2)

// ---------------- PTX helpers ----------------------------------------------
__device__ __forceinline__ uint32_t smem_u32(const void* p) {
    return (uint32_t)__cvta_generic_to_shared(p);
}
__device__ __forceinline__ void cp16(uint32_t dst, const void* src) {
    asm volatile("cp.async.cg.shared.global [%0], [%1], 16;" :: "r"(dst), "l"(src));
}

// packed conversions (2 elts/instr)
__device__ __forceinline__ uint32_t bf16x2_of(float lo, float hi) {
    uint32_t r;
    asm("cvt.rn.bf16x2.f32 %0, %1, %2;" : "=r"(r) : "f"(hi), "f"(lo));
    return r;
}
__device__ __forceinline__ uint32_t e4m3x2_of(float lo, float hi) {
    uint16_t r;
    asm("cvt.rn.satfinite.e4m3x2.f32 %0, %1, %2;" : "=h"(r) : "f"(hi), "f"(lo));
    return (uint32_t)r;
}

#if TC_OK
__device__ __forceinline__ uint32_t ctarank() {
    uint32_t r; asm("mov.u32 %0, %%cluster_ctarank;" : "=r"(r)); return r;
}

#define CP_MBAR_ARRIVE(mb) \
    asm volatile("cp.async.mbarrier.arrive.noinc.shared::cta.b64 [%0];" :: "r"(mb) : "memory")

#define TC_ALLOC2(sa, n)  asm volatile("tcgen05.alloc.cta_group::2.sync.aligned.shared::cta.b32 [%0], %1;" :: "r"(sa), "r"(n) : "memory")
#define TC_DEALLOC2(t, n) asm volatile("tcgen05.dealloc.cta_group::2.sync.aligned.b32 %0, %1;" :: "r"(t), "r"(n))
#define TC_RELINQ2()      asm volatile("tcgen05.relinquish_alloc_permit.cta_group::2.sync.aligned;")
#define TC_COMMIT_MC2(mb, mask) asm volatile("tcgen05.commit.cta_group::2.mbarrier::arrive::one.shared::cluster.multicast::cluster.b64 [%0], %1;" :: "r"(mb), "h"((uint16_t)(mask)) : "memory")
#define TC_WAIT_LD()      asm volatile("tcgen05.wait::ld.sync.aligned;" ::: "memory")
#define TC_FENCE_AFTER()  asm volatile("tcgen05.fence::after_thread_sync;" ::: "memory")
#define TC_FENCE_BEFORE() asm volatile("tcgen05.fence::before_thread_sync;" ::: "memory")
#define FENCE_ASYNC()     asm volatile("fence.proxy.async.shared::cta;" ::: "memory")
#define MBAR_INIT(a, c)   asm volatile("mbarrier.init.shared.b64 [%0], %1;" :: "r"(a), "r"(c) : "memory")
#define CLUSTER_SYNC() do { \
    asm volatile("barrier.cluster.arrive.aligned;" ::: "memory"); \
    asm volatile("barrier.cluster.wait.aligned;"   ::: "memory"); } while (0)

__device__ __forceinline__ void mbar_arrive_cluster(uint32_t addr, uint32_t rank) {
    asm volatile("{\n\t.reg .b32 ra;\n\tmapa.shared::cluster.u32 ra, %0, %1;\n\t"
                 "mbarrier.arrive.shared::cluster.b64 _, [ra];\n\t}"
                 :: "r"(addr), "r"(rank) : "memory");
}

#define MBAR_WAIT(mb, ph) do {                                                    \
    uint32_t _m = (mb), _p = (uint32_t)(ph), _d;                                  \
    asm volatile("{\n\t.reg .pred p;\n\t"                                         \
        "mbarrier.try_wait.parity.acquire.cta.shared::cta.b64 p, [%1], %2;\n\t"   \
        "selp.b32 %0, 1, 0, p;\n\t}" : "=r"(_d) : "r"(_m), "r"(_p) : "memory");   \
    if (!_d) {                                                                    \
        asm volatile("{\n\t.reg .pred P1;\n\tWL_%=:\n\t"                          \
            "mbarrier.try_wait.parity.acquire.cta.shared::cta.b64 P1, [%0], %1, 0x989680;\n\t" \
            "@P1 bra.uni WD_%=;\n\tbra.uni WL_%=;\n\tWD_%=:\n\t}"                 \
            :: "r"(_m), "r"(_p) : "memory");                                      \
    }                                                                             \
} while (0)

#define MBAR_WAIT_CL(mb, ph) do {                                                 \
    uint32_t _m = (mb), _p = (uint32_t)(ph), _d;                                  \
    asm volatile("{\n\t.reg .pred p;\n\t"                                         \
        "mbarrier.try_wait.parity.acquire.cluster.shared::cta.b64 p, [%1], %2;\n\t" \
        "selp.b32 %0, 1, 0, p;\n\t}" : "=r"(_d) : "r"(_m), "r"(_p) : "memory");   \
    if (!_d) {                                                                    \
        asm volatile("{\n\t.reg .pred P1;\n\tWL_%=:\n\t"                          \
            "mbarrier.try_wait.parity.acquire.cluster.shared::cta.b64 P1, [%0], %1, 0x989680;\n\t" \
            "@P1 bra.uni WD_%=;\n\tbra.uni WL_%=;\n\tWD_%=:\n\t}"                 \
            :: "r"(_m), "r"(_p) : "memory");                                      \
    }                                                                             \
} while (0)

#define LDTM32(r, ta)                                                             \
    asm volatile("tcgen05.ld.sync.aligned.32x32b.x32.b32 "                        \
        "{%0,%1,%2,%3,%4,%5,%6,%7,%8,%9,%10,%11,%12,%13,%14,%15,"                 \
        "%16,%17,%18,%19,%20,%21,%22,%23,%24,%25,%26,%27,%28,%29,%30,%31},[%32];" \
        : "=r"((r)[0]),"=r"((r)[1]),"=r"((r)[2]),"=r"((r)[3]),                    \
          "=r"((r)[4]),"=r"((r)[5]),"=r"((r)[6]),"=r"((r)[7]),                    \
          "=r"((r)[8]),"=r"((r)[9]),"=r"((r)[10]),"=r"((r)[11]),                  \
          "=r"((r)[12]),"=r"((r)[13]),"=r"((r)[14]),"=r"((r)[15]),                \
          "=r"((r)[16]),"=r"((r)[17]),"=r"((r)[18]),"=r"((r)[19]),                \
          "=r"((r)[20]),"=r"((r)[21]),"=r"((r)[22]),"=r"((r)[23]),                \
          "=r"((r)[24]),"=r"((r)[25]),"=r"((r)[26]),"=r"((r)[27]),                \
          "=r"((r)[28]),"=r"((r)[29]),"=r"((r)[30]),"=r"((r)[31])                 \
        : "r"(ta))

__device__ __forceinline__ uint64_t sdesc(uint32_t addr) {      // SW128 bf16 tiles
    return 0x4000404000010000ULL | (uint64_t)((addr >> 4) & 0x3FFF);
}
__device__ __forceinline__ uint64_t sdesc64(uint32_t addr) {    // SW64 fp8 tiles
    return (4ull << 61) | (1ull << 46) | (32ull << 32) | (1ull << 16)
         | (uint64_t)((addr >> 4) & 0x3FFF);
}
__device__ __forceinline__ uint32_t sw64(uint32_t o) { return o ^ ((o >> 3) & 0x30); }

__device__ __forceinline__ void mma2(uint32_t d, uint64_t a, uint64_t b,
                                     uint32_t idesc, bool acc) {
    uint32_t en = acc ? 1u : 0u;
    asm volatile("{\n\t.reg .pred p;\n\tsetp.ne.u32 p, %5, 0;\n\t"
        "tcgen05.mma.cta_group::2.kind::f16 [%0], %1, %2, %3, "
        "{%4,%4,%4,%4,%4,%4,%4,%4}, p;\n\t}"
        :: "r"(d), "l"(a), "l"(b), "r"(idesc), "r"(0u), "r"(en) : "memory");
}
__device__ __forceinline__ void mma2_f8(uint32_t d, uint64_t a, uint64_t b,
                                        uint32_t idesc) {
    asm volatile("{\n\t.reg .pred p;\n\tsetp.ne.u32 p, 1, 0;\n\t"
        "tcgen05.mma.cta_group::2.kind::f8f6f4 [%0], %1, %2, %3, "
        "{%4,%4,%4,%4,%4,%4,%4,%4}, p;\n\t}"
        :: "r"(d), "l"(a), "l"(b), "r"(idesc), "r"(0u) : "memory");
}

#define IDESC2    ((1u << 4) | (1u << 7) | (1u << 10) | ((256u / 8) << 17) | ((256u / 16) << 24))
#define IDESC2_F8 ((1u << 4) | ((256u / 8) << 17) | ((256u / 16) << 24))
#endif // TC_OK

// ---------------- fused pre-pass (static block partition, packed cvt) --------
#define PREP_WB   1280                   // blocks per weight matrix
#define PREP_XB   256                    // blocks for x
#define PREP_NB   (3 * PREP_WB + PREP_XB)

__global__ void __launch_bounds__(256) prep(const int* __restrict__ gw,
                                            const int* __restrict__ uw,
                                            const int* __restrict__ dw,
                                            const float* __restrict__ x) {
    const int b = blockIdx.x;
    if (b < 3 * PREP_WB) {
        const int sel = b / PREP_WB;                    // once per block
        const int rb  = b - sel * PREP_WB;
        const int* __restrict__ w = (sel == 0) ? gw : (sel == 1) ? uw : dw;
        __nv_bfloat16* o  = (sel == 0) ? g_wg : (sel == 1) ? g_wu : g_wd;
        unsigned char* o8 = (sel == 0) ? g_w8g : (sel == 1) ? g_w8u : g_w8d;
        const float sc8 = (sel == 2) ? 0.5f : (1.0f / 64.0f);
        const long n4 = (long)KI * KD / 4;
        const long step = (long)PREP_WB * 256;
        for (long j = (long)rb * 256 + threadIdx.x; j < n4; j += step) {
            const int4 v = __ldcs(&((const int4*)w)[j]);
            const float f0 = (float)v.x, f1 = (float)v.y;
            const float f2 = (float)v.z, f3 = (float)v.w;
            uint2 pb;
            pb.x = bf16x2_of(f0, f1);
            pb.y = bf16x2_of(f2, f3);
            __stcs(&((uint2*)o)[j], pb);
            const uint32_t q = e4m3x2_of(f0 * sc8, f1 * sc8)
                             | (e4m3x2_of(f2 * sc8, f3 * sc8) << 16);
            __stcs(&((uint32_t*)o8)[j], q);
        }
    } else {
        const int rb = b - 3 * PREP_WB;
        const long x4 = (long)KM * KD / 4;
        const long step = (long)PREP_XB * 256;
        for (long i = (long)rb * 256 + threadIdx.x; i < x4; i += step) {
            const float4 v = __ldcs(&((const float4*)x)[i]);
            const uint32_t h01 = bf16x2_of(v.x, v.y);
            const uint32_t h23 = bf16x2_of(v.z, v.w);
            // recover hi values as floats: lo lane = <<16, hi lane = mask
            const float a0 = __uint_as_float(h01 << 16);
            const float a1 = __uint_as_float(h01 & 0xFFFF0000u);
            const float a2 = __uint_as_float(h23 << 16);
            const float a3 = __uint_as_float(h23 & 0xFFFF0000u);
            uint2 ph; ph.x = h01; ph.y = h23;
            __stcs(&((uint2*)g_xh)[i], ph);
            const uint32_t l = e4m3x2_of((v.x - a0) * 64.0f, (v.y - a1) * 64.0f)
                             | (e4m3x2_of((v.z - a2) * 64.0f, (v.w - a3) * 64.0f) << 16);
            __stcs(&((uint32_t*)g_x8l)[i], l);
        }
    }
}

// ---------------- persistent GEMMs -------------------------------------------
#define NPAIR    74
#define NTHR     288
// stage: [AH 16K][B0 16K][B1 16K][AL8 8K][B0L8 8K][B1L8 8K] = 72 KB
#define SST      73728
#define OF_AH    0
#define OF_B0    16384
#define OF_B1    32768
#define OF_AL    49152
#define OF_B0L   57344
#define OF_B1L   65536
#define GSMEM    (3 * SST + 1024)

#define K1_NC    (KD / 64)
#define K1_NT    (KI / 256)
#define K1_GM    16
#define K1_TILES (K1_NT * (KM / 256))    // 1376
#define K2_NC    (KI / 64)
#define K2_NT    (KD / 512)
#define K2_GM    8
#define K2_TILES (K2_NT * (KM / 256))    // 256

extern __shared__ char dsm[];

// ---------------- K1: fused gate+up, persistent ------------------------------
__global__ void __launch_bounds__(NTHR, 1) __cluster_dims__(2, 1, 1)
k1(const float* __restrict__ gs_p, const float* __restrict__ us_p)
{
#if TC_OK
    const int t = threadIdx.x, wid = t >> 5, lane = t & 31;
    const uint32_t rank = ctarank();
    const int pair = blockIdx.y;
    const uint32_t sb = (smem_u32(dsm) + 1023u) & ~1023u;

    __shared__ uint32_t s_tm[1];
    __shared__ alignas(8) uint64_t s_mb[11];  // full[3], rdy[3], done[3], tdone, epi

    if (wid == 8) TC_ALLOC2(smem_u32(s_tm), 512);
    if (t == 0) {
#pragma unroll
        for (int i = 0; i < 3; ++i) {
            MBAR_INIT(smem_u32(&s_mb[i]),     128);
            MBAR_INIT(smem_u32(&s_mb[3 + i]), 2);
            MBAR_INIT(smem_u32(&s_mb[6 + i]), 1);
        }
        MBAR_INIT(smem_u32(&s_mb[9]),  1);
        MBAR_INIT(smem_u32(&s_mb[10]), 2);
    }
    __syncthreads();
    CLUSTER_SYNC();
    uint32_t tm;
    asm volatile("ld.shared.b32 %0, [%1];" : "=r"(tm) : "r"(smem_u32(s_tm)));
    const uint32_t full0 = smem_u32(&s_mb[0]), rdy0 = smem_u32(&s_mb[3]);
    const uint32_t done0 = smem_u32(&s_mb[6]);
    const uint32_t tdone = smem_u32(&s_mb[9]), epib = smem_u32(&s_mb[10]);

    if (t >= 128 && t < 256) {
        // ---------------- producers ----------------
        const int tp  = t - 128;
        const int c16 = tp & 7;
        const int r0  = tp >> 3;
        const uint32_t swc = (uint32_t)((c16 ^ (r0 & 7)) * 16);
        const int c4  = tp & 3;
        const int r4  = tp >> 2;
        long q = 0;
        for (int idx = pair; idx < K1_TILES; idx += NPAIR) {
            const int band = idx / (K1_NT * K1_GM);
            const int rsub = idx % (K1_NT * K1_GM);
            const int n0   = (rsub / K1_GM) * 256;
            const int mp   = band * K1_GM + rsub % K1_GM;
            const int m0   = (mp * 2 + (int)rank) * 128;
            const __nv_bfloat16* pxh = g_xh + (size_t)(m0 + r0) * KD + c16 * 8;
            const __nv_bfloat16* pg  = g_wg + (size_t)(n0 + rank * 128 + r0) * KD + c16 * 8;
            const __nv_bfloat16* pu  = g_wu + (size_t)(n0 + rank * 128 + r0) * KD + c16 * 8;
            const unsigned char* pxl = g_x8l + (size_t)(m0 + r4) * KD + c4 * 16;
            const unsigned char* pg8 = g_w8g + (size_t)(n0 + rank * 128 + r4) * KD + c4 * 16;
            const unsigned char* pu8 = g_w8u + (size_t)(n0 + rank * 128 + r4) * KD + c4 * 16;
            for (int c = 0; c < K1_NC; ++c, ++q) {
                const int s = (int)(q % 3);
                if (q >= 3) MBAR_WAIT(done0 + s * 8, (int)((q / 3 - 1) & 1));
                const int k0 = c * 64;
                const uint32_t st = sb + s * SST;
#pragma unroll
                for (int i = 0; i < 8; ++i) {
                    const uint32_t d = (uint32_t)((r0 + 16 * i) * 128) + swc;
                    const size_t go = (size_t)(16 * i) * KD + k0;
                    cp16(st + OF_AH + d, pxh + go);
                    cp16(st + OF_B0 + d, pg + go);
                    cp16(st + OF_B1 + d, pu + go);
                }
#pragma unroll
                for (int i = 0; i < 4; ++i) {
                    const uint32_t o = (uint32_t)((r4 + 32 * i) * 64 + c4 * 16);
                    const uint32_t d = sw64(o);
                    const size_t go = (size_t)(32 * i) * KD + k0;
                    cp16(st + OF_AL  + d, pxl + go);
                    cp16(st + OF_B0L + d, pg8 + go);
                    cp16(st + OF_B1L + d, pu8 + go);
                }
                CP_MBAR_ARRIVE(full0 + s * 8);
            }
        }
    } else if (t == 257) {
        // ---------------- relay ----------------
        long q = 0;
        for (int idx = pair; idx < K1_TILES; idx += NPAIR)
            for (int c = 0; c < K1_NC; ++c, ++q) {
                const int s = (int)(q % 3);
                MBAR_WAIT(full0 + s * 8, (int)((q / 3) & 1));
                FENCE_ASYNC();
                mbar_arrive_cluster(rdy0 + s * 8, 0);
            }
    } else if (rank == 0 && t == 256) {
        // ---------------- MMA leader ----------------
        long q = 0; int it = 0;
        for (int idx = pair; idx < K1_TILES; idx += NPAIR, ++it) {
            if (it > 0) MBAR_WAIT_CL(epib, (it - 1) & 1);
            for (int c = 0; c < K1_NC; ++c, ++q) {
                const int s = (int)(q % 3);
                MBAR_WAIT_CL(rdy0 + s * 8, (int)((q / 3) & 1));
                const uint32_t st = sb + s * SST;
                const uint64_t da = sdesc(st + OF_AH);
                const uint64_t dg = sdesc(st + OF_B0), du = sdesc(st + OF_B1);
                const uint64_t dal = sdesc64(st + OF_AL);
                const uint64_t dgl = sdesc64(st + OF_B0L), dul = sdesc64(st + OF_B1L);
#pragma unroll
                for (int k = 0; k < 4; ++k) {
                    const bool acc = (c > 0) || (k > 0);
                    mma2(tm,       da + 2 * k, dg + 2 * k, IDESC2, acc);
                    mma2(tm + 256, da + 2 * k, du + 2 * k, IDESC2, acc);
                }
#pragma unroll
                for (int k = 0; k < 2; ++k) {
                    mma2_f8(tm,       dal + 2 * k, dgl + 2 * k, IDESC2_F8);
                    mma2_f8(tm + 256, dal + 2 * k, dul + 2 * k, IDESC2_F8);
                }
                TC_COMMIT_MC2(done0 + s * 8, 0x3);
                if (c == K1_NC - 1) TC_COMMIT_MC2(tdone, 0x3);
            }
        }
    } else if (t < 128) {
        // ---------------- consumers (epilogue) ----------------
        const float gsc = gs_p[0], usc = us_p[0];
        int it = 0;
        for (int idx = pair; idx < K1_TILES; idx += NPAIR, ++it) {
            const int band = idx / (K1_NT * K1_GM);
            const int rsub = idx % (K1_NT * K1_GM);
            const int n0   = (rsub / K1_GM) * 256;
            const int mp   = band * K1_GM + rsub % K1_GM;
            const int m0   = (mp * 2 + (int)rank) * 128;
            MBAR_WAIT(tdone, it & 1);
            TC_FENCE_AFTER();
            const int m = m0 + wid * 32 + lane;
#pragma unroll 1
            for (int cb = 0; cb < 8; ++cb) {
                uint32_t rg[32], ru[32];
                LDTM32(rg, tm + cb * 32);
                LDTM32(ru, tm + 256 + cb * 32);
                TC_WAIT_LD();
                alignas(16) ushort oh[32];
                alignas(16) unsigned char ol8[32];
#pragma unroll
                for (int j = 0; j < 32; ++j) {
                    const float g = __uint_as_float(rg[j]) * gsc;
                    const float u = __uint_as_float(ru[j]) * usc;
                    const float v = (g / (1.0f + __expf(-g))) * u;
                    const __nv_bfloat16 hh = __float2bfloat16(v);
                    oh[j] = *(const ushort*)&hh;
                    ol8[j] = __nv_fp8_e4m3((v - __bfloat162float(hh)) * 2.0f).__x;
                }
                const size_t eoff = (size_t)m * KI + n0 + cb * 32;
#pragma unroll
                for (int qq = 0; qq < 4; ++qq)
                    *(uint4*)((char*)g_hh + eoff * 2 + qq * 16) = *(uint4*)&oh[qq * 8];
#pragma unroll
                for (int qq = 0; qq < 2; ++qq)
                    *(uint4*)(g_h8l + eoff + qq * 16) = *(uint4*)&ol8[qq * 16];
            }
            TC_FENCE_BEFORE();
            asm volatile("bar.sync 1, 128;" ::: "memory");
            if (t == 0) mbar_arrive_cluster(epib, 0);
        }
    }
    __syncthreads();
    if (wid == 8) { TC_RELINQ2(); TC_DEALLOC2(tm, 512); }
    CLUSTER_SYNC();

#else  // SIMT fallback (compile-only; never runs on GB300)
    const int t = threadIdx.x;
    const float gsc = gs_p[0], usc = us_p[0];
    for (int idx = blockIdx.y; idx < K1_TILES; idx += NPAIR) {
        const int band = idx / (K1_NT * K1_GM);
        const int rsub = idx % (K1_NT * K1_GM);
        const int n0   = (rsub / K1_GM) * 256;
        const int mp   = band * K1_GM + rsub % K1_GM;
        const int m0   = (mp * 2 + blockIdx.x) * 128;
        for (int e = t; e < 128 * 256; e += blockDim.x) {
            const int r = e >> 8, col = e & 255;
            const int m = m0 + r;
            float ag = 0.f, au = 0.f;
            for (int k = 0; k < KD; ++k) {
                const float xv = __bfloat162float(g_xh[(size_t)m * KD + k]);
                ag += xv * __bfloat162float(g_wg[(size_t)(n0 + col) * KD + k]);
                au += xv * __bfloat162float(g_wu[(size_t)(n0 + col) * KD + k]);
            }
            const float g = ag * gsc;
            const float v = (g / (1.0f + __expf(-g))) * (au * usc);
            const __nv_bfloat16 hh = __float2bfloat16(v);
            g_hh[(size_t)m * KI + n0 + col] = hh;
            g_h8l[(size_t)m * KI + n0 + col] =
                __nv_fp8_e4m3((v - __bfloat162float(hh)) * 2.0f).__x;
        }
    }
#endif
}

// ---------------- K2: down GEMM, persistent -----------------------------------
__global__ void __launch_bounds__(NTHR, 1) __cluster_dims__(2, 1, 1)
k2(const float* __restrict__ ds_p, float* __restrict__ out)
{
#if TC_OK
    const int t = threadIdx.x, wid = t >> 5, lane = t & 31;
    const uint32_t rank = ctarank();
    const int pair = blockIdx.y;
    const uint32_t sb = (smem_u32(dsm) + 1023u) & ~1023u;

    __shared__ uint32_t s_tm[1];
    __shared__ alignas(8) uint64_t s_mb[11];

    if (wid == 8) TC_ALLOC2(smem_u32(s_tm), 512);
    if (t == 0) {
#pragma unroll
        for (int i = 0; i < 3; ++i) {
            MBAR_INIT(smem_u32(&s_mb[i]),     128);
            MBAR_INIT(smem_u32(&s_mb[3 + i]), 2);
            MBAR_INIT(smem_u32(&s_mb[6 + i]), 1);
        }
        MBAR_INIT(smem_u32(&s_mb[9]),  1);
        MBAR_INIT(smem_u32(&s_mb[10]), 2);
    }
    __syncthreads();
    CLUSTER_SYNC();
    uint32_t tm;
    asm volatile("ld.shared.b32 %0, [%1];" : "=r"(tm) : "r"(smem_u32(s_tm)));
    const uint32_t full0 = smem_u32(&s_mb[0]), rdy0 = smem_u32(&s_mb[3]);
    const uint32_t done0 = smem_u32(&s_mb[6]);
    const uint32_t tdone = smem_u32(&s_mb[9]), epib = smem_u32(&s_mb[10]);

    if (t >= 128 && t < 256) {
        // ---------------- producers ----------------
        const int tp  = t - 128;
        const int c16 = tp & 7;
        const int r0  = tp >> 3;
        const uint32_t swc = (uint32_t)((c16 ^ (r0 & 7)) * 16);
        const int c4  = tp & 3;
        const int r4  = tp >> 2;
        long q = 0;
        for (int idx = pair; idx < K2_TILES; idx += NPAIR) {
            const int band = idx / (K2_NT * K2_GM);
            const int rsub = idx % (K2_NT * K2_GM);
            const int n0   = (rsub / K2_GM) * 512;
            const int mp   = band * K2_GM + rsub % K2_GM;
            const int m0   = (mp * 2 + (int)rank) * 128;
            const __nv_bfloat16* pah = g_hh + (size_t)(m0 + r0) * KI + c16 * 8;
            const __nv_bfloat16* pb0 = g_wd + (size_t)(n0 +       rank * 128 + r0) * KI + c16 * 8;
            const __nv_bfloat16* pb1 = g_wd + (size_t)(n0 + 256 + rank * 128 + r0) * KI + c16 * 8;
            const unsigned char* pal = g_h8l + (size_t)(m0 + r4) * KI + c4 * 16;
            const unsigned char* p08 = g_w8d + (size_t)(n0 +       rank * 128 + r4) * KI + c4 * 16;
            const unsigned char* p18 = g_w8d + (size_t)(n0 + 256 + rank * 128 + r4) * KI + c4 * 16;
            for (int c = 0; c < K2_NC; ++c, ++q) {
                const int s = (int)(q % 3);
                if (q >= 3) MBAR_WAIT(done0 + s * 8, (int)((q / 3 - 1) & 1));
                const int k0 = c * 64;
                const uint32_t st = sb + s * SST;
#pragma unroll
                for (int i = 0; i < 8; ++i) {
                    const uint32_t d = (uint32_t)((r0 + 16 * i) * 128) + swc;
                    const size_t go = (size_t)(16 * i) * KI + k0;
                    cp16(st + OF_AH + d, pah + go);
                    cp16(st + OF_B0 + d, pb0 + go);
                    cp16(st + OF_B1 + d, pb1 + go);
                }
#pragma unroll
                for (int i = 0; i < 4; ++i) {
                    const uint32_t o = (uint32_t)((r4 + 32 * i) * 64 + c4 * 16);
                    const uint32_t d = sw64(o);
                    const size_t go = (size_t)(32 * i) * KI + k0;
                    cp16(st + OF_AL  + d, pal + go);
                    cp16(st + OF_B0L + d, p08 + go);
                    cp16(st + OF_B1L + d, p18 + go);
                }
                CP_MBAR_ARRIVE(full0 + s * 8);
            }
        }
    } else if (t == 257) {
        long q = 0;
        for (int idx = pair; idx < K2_TILES; idx += NPAIR)
            for (int c = 0; c < K2_NC; ++c, ++q) {
                const int s = (int)(q % 3);
                MBAR_WAIT(full0 + s * 8, (int)((q / 3) & 1));
                FENCE_ASYNC();
                mbar_arrive_cluster(rdy0 + s * 8, 0);
            }
    } else if (rank == 0 && t == 256) {
        long q = 0; int it = 0;
        for (int idx = pair; idx < K2_TILES; idx += NPAIR, ++it) {
            if (it > 0) MBAR_WAIT_CL(epib, (it - 1) & 1);
            for (int c = 0; c < K2_NC; ++c, ++q) {
                const int s = (int)(q % 3);
                MBAR_WAIT_CL(rdy0 + s * 8, (int)((q / 3) & 1));
                const uint32_t st = sb + s * SST;
                const uint64_t da = sdesc(st + OF_AH);
                const uint64_t d0 = sdesc(st + OF_B0), d1 = sdesc(st + OF_B1);
                const uint64_t dal = sdesc64(st + OF_AL);
                const uint64_t d0l = sdesc64(st + OF_B0L), d1l = sdesc64(st + OF_B1L);
#pragma unroll
                for (int k = 0; k < 4; ++k) {
                    const bool acc = (c > 0) || (k > 0);
                    mma2(tm,       da + 2 * k, d0 + 2 * k, IDESC2, acc);
                    mma2(tm + 256, da + 2 * k, d1 + 2 * k, IDESC2, acc);
                }
#pragma unroll
                for (int k = 0; k < 2; ++k) {
                    mma2_f8(tm,       dal + 2 * k, d0l + 2 * k, IDESC2_F8);
                    mma2_f8(tm + 256, dal + 2 * k, d1l + 2 * k, IDESC2_F8);
                }
                TC_COMMIT_MC2(done0 + s * 8, 0x3);
                if (c == K2_NC - 1) TC_COMMIT_MC2(tdone, 0x3);
            }
        }
    } else if (t < 128) {
        const float dsc = ds_p[0];
        int it = 0;
        for (int idx = pair; idx < K2_TILES; idx += NPAIR, ++it) {
            const int band = idx / (K2_NT * K2_GM);
            const int rsub = idx % (K2_NT * K2_GM);
            const int n0   = (rsub / K2_GM) * 512;
            const int mp   = band * K2_GM + rsub % K2_GM;
            const int m0   = (mp * 2 + (int)rank) * 128;
            MBAR_WAIT(tdone, it & 1);
            TC_FENCE_AFTER();
            const int m = m0 + wid * 32 + lane;
#pragma unroll 1
            for (int cb = 0; cb < 16; ++cb) {
                uint32_t r[32];
                LDTM32(r, tm + cb * 32);
                TC_WAIT_LD();
                float* p = out + (size_t)m * KD + n0 + cb * 32;
#pragma unroll
                for (int qq = 0; qq < 8; ++qq) {
                    float4 v;
                    v.x = __uint_as_float(r[qq * 4 + 0]) * dsc;
                    v.y = __uint_as_float(r[qq * 4 + 1]) * dsc;
                    v.z = __uint_as_float(r[qq * 4 + 2]) * dsc;
                    v.w = __uint_as_float(r[qq * 4 + 3]) * dsc;
                    *(float4*)(p + qq * 4) = v;
                }
            }
            TC_FENCE_BEFORE();
            asm volatile("bar.sync 1, 128;" ::: "memory");
            if (t == 0) mbar_arrive_cluster(epib, 0);
        }
    }
    __syncthreads();
    if (wid == 8) { TC_RELINQ2(); TC_DEALLOC2(tm, 512); }
    CLUSTER_SYNC();

#else  // SIMT fallback (compile-only)
    const int t = threadIdx.x;
    const float dsc = ds_p[0];
    for (int idx = blockIdx.y; idx < K2_TILES; idx += NPAIR) {
        const int band = idx / (K2_NT * K2_GM);
        const int rsub = idx % (K2_NT * K2_GM);
        const int n0   = (rsub / K2_GM) * 512;
        const int mp   = band * K2_GM + rsub % K2_GM;
        const int m0   = (mp * 2 + blockIdx.x) * 128;
        for (int e = t; e < 128 * 512; e += blockDim.x) {
            const int r = e >> 9, col = e & 511;
            const int m = m0 + r;
            float acc = 0.f;
            for (int k = 0; k < KI; ++k)
                acc += __bfloat162float(g_hh[(size_t)m * KI + k])
                     * __bfloat162float(g_wd[(size_t)(n0 + col) * KI + k]);
            out[(size_t)m * KD + n0 + col] = acc * dsc;
        }
    }
#endif
}

// ---------------- launch ------------------------------------------------------
extern "C" void kernel_launch(void* const* d_in, const int* in_sizes, int n_in,
                              void* d_out, int out_size)
{
    const float* x  = (const float*)d_in[0];
    const int*   gw = (const int*)  d_in[1];
    const float* gs = (const float*)d_in[2];
    const int*   uw = (const int*)  d_in[3];
    const float* us = (const float*)d_in[4];
    const int*   dw = (const int*)  d_in[5];
    const float* ds = (const float*)d_in[6];
    float* out = (float*)d_out;

    cudaFuncSetAttribute(k1, cudaFuncAttributeMaxDynamicSharedMemorySize, GSMEM);
    cudaFuncSetAttribute(k2, cudaFuncAttributeMaxDynamicSharedMemorySize, GSMEM);

    prep<<<PREP_NB, 256>>>(gw, uw, dw, x);

    k1<<<dim3(2, NPAIR, 1), NTHR, GSMEM>>>(gs, us);
    k2<<<dim3(2, NPAIR, 1), NTHR, GSMEM>>>(ds, out);
}

// round 15
// speedup vs baseline: 1.4326x; 1.0412x over previous
#include <cuda_runtime.h>
#include <cuda_bf16.h>
#include <cuda_fp8.h>
#include <cstdint>
#include <math.h>

#define KD 4096
#define KI 11008
#define KM 8192

#if !defined(__CUDA_ARCH__) || defined(__CUDA_ARCH_FEAT_SM103_ALL)
#define TC_OK 1
#else
#define TC_OK 0
#endif

// ---------------- persistent scratch (__device__ globals; no allocs) -------
__device__ __nv_bfloat16 g_wg[(size_t)KI * KD];   // gate w bf16 [I,D]
__device__ __nv_bfloat16 g_wu[(size_t)KI * KD];   // up   w bf16 [I,D]
__device__ __nv_bfloat16 g_wd[(size_t)KD * KI];   // down w bf16 [D,I]
__device__ unsigned char g_w8g[(size_t)KI * KD];  // e4m3(gate/64)
__device__ unsigned char g_w8u[(size_t)KI * KD];  // e4m3(up/64)
__device__ unsigned char g_w8d[(size_t)KD * KI];  // e4m3(down/2)
__device__ __nv_bfloat16 g_xh[(size_t)KM * KD];   // x hi bf16
__device__ unsigned char g_x8l[(size_t)KM * KD];  // e4m3((x-xh)*64)
__device__ __nv_bfloat16 g_hh[(size_t)KM * KI];   // h hi bf16
__device__ unsigned char g_h8l[(size_t)KM * KI];  // e4m3((h-hh)*2)
__device__ int           g_rdy[KM / 256];         // per-m-pair readiness (0..86)

// ---------------- PTX helpers ----------------------------------------------
__device__ __forceinline__ uint32_t smem_u32(const void* p) {
    return (uint32_t)__cvta_generic_to_shared(p);
}
__device__ __forceinline__ void cp16(uint32_t dst, const void* src) {
    asm volatile("cp.async.cg.shared.global [%0], [%1], 16;" :: "r"(dst), "l"(src));
}
__device__ __forceinline__ uint32_t bf16x2_of(float lo, float hi) {
    uint32_t r;
    asm("cvt.rn.bf16x2.f32 %0, %1, %2;" : "=r"(r) : "f"(hi), "f"(lo));
    return r;
}
__device__ __forceinline__ uint32_t e4m3x2_of(float lo, float hi) {
    uint16_t r;
    asm("cvt.rn.satfinite.e4m3x2.f32 %0, %1, %2;" : "=h"(r) : "f"(hi), "f"(lo));
    return (uint32_t)r;
}

#if TC_OK
__device__ __forceinline__ uint32_t ctarank() {
    uint32_t r; asm("mov.u32 %0, %%cluster_ctarank;" : "=r"(r)); return r;
}

#define CP_MBAR_ARRIVE(mb) \
    asm volatile("cp.async.mbarrier.arrive.noinc.shared::cta.b64 [%0];" :: "r"(mb) : "memory")

#define TC_ALLOC2(sa, n)  asm volatile("tcgen05.alloc.cta_group::2.sync.aligned.shared::cta.b32 [%0], %1;" :: "r"(sa), "r"(n) : "memory")
#define TC_DEALLOC2(t, n) asm volatile("tcgen05.dealloc.cta_group::2.sync.aligned.b32 %0, %1;" :: "r"(t), "r"(n))
#define TC_RELINQ2()      asm volatile("tcgen05.relinquish_alloc_permit.cta_group::2.sync.aligned;")
#define TC_COMMIT_MC2(mb, mask) asm volatile("tcgen05.commit.cta_group::2.mbarrier::arrive::one.shared::cluster.multicast::cluster.b64 [%0], %1;" :: "r"(mb), "h"((uint16_t)(mask)) : "memory")
#define TC_WAIT_LD()      asm volatile("tcgen05.wait::ld.sync.aligned;" ::: "memory")
#define TC_FENCE_AFTER()  asm volatile("tcgen05.fence::after_thread_sync;" ::: "memory")
#define TC_FENCE_BEFORE() asm volatile("tcgen05.fence::before_thread_sync;" ::: "memory")
#define FENCE_ASYNC()     asm volatile("fence.proxy.async.shared::cta;" ::: "memory")
#define MBAR_INIT(a, c)   asm volatile("mbarrier.init.shared.b64 [%0], %1;" :: "r"(a), "r"(c) : "memory")
#define CLUSTER_SYNC() do { \
    asm volatile("barrier.cluster.arrive.aligned;" ::: "memory"); \
    asm volatile("barrier.cluster.wait.aligned;"   ::: "memory"); } while (0)

__device__ __forceinline__ void mbar_arrive_cluster(uint32_t addr, uint32_t rank) {
    asm volatile("{\n\t.reg .b32 ra;\n\tmapa.shared::cluster.u32 ra, %0, %1;\n\t"
                 "mbarrier.arrive.shared::cluster.b64 _, [ra];\n\t}"
                 :: "r"(addr), "r"(rank) : "memory");
}
__device__ __forceinline__ void rdy_release(int* p) {
    asm volatile("red.release.gpu.global.add.s32 [%0], 1;" :: "l"(p) : "memory");
}
__device__ __forceinline__ int rdy_acquire(const int* p) {
    int v;
    asm volatile("ld.acquire.gpu.global.b32 %0, [%1];" : "=r"(v) : "l"(p) : "memory");
    return v;
}

#define MBAR_WAIT(mb, ph) do {                                                    \
    uint32_t _m = (mb), _p = (uint32_t)(ph), _d;                                  \
    asm volatile("{\n\t.reg .pred p;\n\t"                                         \
        "mbarrier.try_wait.parity.acquire.cta.shared::cta.b64 p, [%1], %2;\n\t"   \
        "selp.b32 %0, 1, 0, p;\n\t}" : "=r"(_d) : "r"(_m), "r"(_p) : "memory");   \
    if (!_d) {                                                                    \
        asm volatile("{\n\t.reg .pred P1;\n\tWL_%=:\n\t"                          \
            "mbarrier.try_wait.parity.acquire.cta.shared::cta.b64 P1, [%0], %1, 0x989680;\n\t" \
            "@P1 bra.uni WD_%=;\n\tbra.uni WL_%=;\n\tWD_%=:\n\t}"                 \
            :: "r"(_m), "r"(_p) : "memory");                                      \
    }                                                                             \
} while (0)

#define MBAR_WAIT_CL(mb, ph) do {                                                 \
    uint32_t _m = (mb), _p = (uint32_t)(ph), _d;                                  \
    asm volatile("{\n\t.reg .pred p;\n\t"                                         \
        "mbarrier.try_wait.parity.acquire.cluster.shared::cta.b64 p, [%1], %2;\n\t" \
        "selp.b32 %0, 1, 0, p;\n\t}" : "=r"(_d) : "r"(_m), "r"(_p) : "memory");   \
    if (!_d) {                                                                    \
        asm volatile("{\n\t.reg .pred P1;\n\tWL_%=:\n\t"                          \
            "mbarrier.try_wait.parity.acquire.cluster.shared::cta.b64 P1, [%0], %1, 0x989680;\n\t" \
            "@P1 bra.uni WD_%=;\n\tbra.uni WL_%=;\n\tWD_%=:\n\t}"                 \
            :: "r"(_m), "r"(_p) : "memory");                                      \
    }                                                                             \
} while (0)

#define LDTM32(r, ta)                                                             \
    asm volatile("tcgen05.ld.sync.aligned.32x32b.x32.b32 "                        \
        "{%0,%1,%2,%3,%4,%5,%6,%7,%8,%9,%10,%11,%12,%13,%14,%15,"                 \
        "%16,%17,%18,%19,%20,%21,%22,%23,%24,%25,%26,%27,%28,%29,%30,%31},[%32];" \
        : "=r"((r)[0]),"=r"((r)[1]),"=r"((r)[2]),"=r"((r)[3]),                    \
          "=r"((r)[4]),"=r"((r)[5]),"=r"((r)[6]),"=r"((r)[7]),                    \
          "=r"((r)[8]),"=r"((r)[9]),"=r"((r)[10]),"=r"((r)[11]),                  \
          "=r"((r)[12]),"=r"((r)[13]),"=r"((r)[14]),"=r"((r)[15]),                \
          "=r"((r)[16]),"=r"((r)[17]),"=r"((r)[18]),"=r"((r)[19]),                \
          "=r"((r)[20]),"=r"((r)[21]),"=r"((r)[22]),"=r"((r)[23]),                \
          "=r"((r)[24]),"=r"((r)[25]),"=r"((r)[26]),"=r"((r)[27]),                \
          "=r"((r)[28]),"=r"((r)[29]),"=r"((r)[30]),"=r"((r)[31])                 \
        : "r"(ta))

__device__ __forceinline__ uint64_t sdesc(uint32_t addr) {      // SW128 bf16 tiles
    return 0x4000404000010000ULL | (uint64_t)((addr >> 4) & 0x3FFF);
}
__device__ __forceinline__ uint64_t sdesc64(uint32_t addr) {    // SW64 fp8 tiles
    return (4ull << 61) | (1ull << 46) | (32ull << 32) | (1ull << 16)
         | (uint64_t)((addr >> 4) & 0x3FFF);
}
__device__ __forceinline__ uint32_t sw64(uint32_t o) { return o ^ ((o >> 3) & 0x30); }

__device__ __forceinline__ void mma2(uint32_t d, uint64_t a, uint64_t b,
                                     uint32_t idesc, bool acc) {
    uint32_t en = acc ? 1u : 0u;
    asm volatile("{\n\t.reg .pred p;\n\tsetp.ne.u32 p, %5, 0;\n\t"
        "tcgen05.mma.cta_group::2.kind::f16 [%0], %1, %2, %3, "
        "{%4,%4,%4,%4,%4,%4,%4,%4}, p;\n\t}"
        :: "r"(d), "l"(a), "l"(b), "r"(idesc), "r"(0u), "r"(en) : "memory");
}
__device__ __forceinline__ void mma2_f8(uint32_t d, uint64_t a, uint64_t b,
                                        uint32_t idesc) {
    asm volatile("{\n\t.reg .pred p;\n\tsetp.ne.u32 p, 1, 0;\n\t"
        "tcgen05.mma.cta_group::2.kind::f8f6f4 [%0], %1, %2, %3, "
        "{%4,%4,%4,%4,%4,%4,%4,%4}, p;\n\t}"
        :: "r"(d), "l"(a), "l"(b), "r"(idesc), "r"(0u) : "memory");
}

#define IDESC2    ((1u << 4) | (1u << 7) | (1u << 10) | ((256u / 8) << 17) | ((256u / 16) << 24))
#define IDESC2_F8 ((1u << 4) | ((256u / 8) << 17) | ((256u / 16) << 24))
#endif // TC_OK

// ---------------- fused pre-pass (static block partition, packed cvt) --------
#define PREP_WB   1280
#define PREP_XB   256
#define PREP_NB   (3 * PREP_WB + PREP_XB)

__global__ void __launch_bounds__(256) prep(const int* __restrict__ gw,
                                            const int* __restrict__ uw,
                                            const int* __restrict__ dw,
                                            const float* __restrict__ x) {
    const int b = blockIdx.x;
    if (b == 0 && threadIdx.x < KM / 256) g_rdy[threadIdx.x] = 0;  // reset handoff
    if (b < 3 * PREP_WB) {
        const int sel = b / PREP_WB;
        const int rb  = b - sel * PREP_WB;
        const int* __restrict__ w = (sel == 0) ? gw : (sel == 1) ? uw : dw;
        __nv_bfloat16* o  = (sel == 0) ? g_wg : (sel == 1) ? g_wu : g_wd;
        unsigned char* o8 = (sel == 0) ? g_w8g : (sel == 1) ? g_w8u : g_w8d;
        const float sc8 = (sel == 2) ? 0.5f : (1.0f / 64.0f);
        const long n4 = (long)KI * KD / 4;
        const long step = (long)PREP_WB * 256;
        for (long j = (long)rb * 256 + threadIdx.x; j < n4; j += step) {
            const int4 v = __ldcs(&((const int4*)w)[j]);
            const float f0 = (float)v.x, f1 = (float)v.y;
            const float f2 = (float)v.z, f3 = (float)v.w;
            uint2 pb;
            pb.x = bf16x2_of(f0, f1);
            pb.y = bf16x2_of(f2, f3);
            __stcs(&((uint2*)o)[j], pb);
            const uint32_t q = e4m3x2_of(f0 * sc8, f1 * sc8)
                             | (e4m3x2_of(f2 * sc8, f3 * sc8) << 16);
            __stcs(&((uint32_t*)o8)[j], q);
        }
    } else {
        const int rb = b - 3 * PREP_WB;
        const long x4 = (long)KM * KD / 4;
        const long step = (long)PREP_XB * 256;
        for (long i = (long)rb * 256 + threadIdx.x; i < x4; i += step) {
            const float4 v = __ldcs(&((const float4*)x)[i]);
            const uint32_t h01 = bf16x2_of(v.x, v.y);
            const uint32_t h23 = bf16x2_of(v.z, v.w);
            const float a0 = __uint_as_float(h01 << 16);
            const float a1 = __uint_as_float(h01 & 0xFFFF0000u);
            const float a2 = __uint_as_float(h23 << 16);
            const float a3 = __uint_as_float(h23 & 0xFFFF0000u);
            uint2 ph; ph.x = h01; ph.y = h23;
            __stcs(&((uint2*)g_xh)[i], ph);
            const uint32_t l = e4m3x2_of((v.x - a0) * 64.0f, (v.y - a1) * 64.0f)
                             | (e4m3x2_of((v.z - a2) * 64.0f, (v.w - a3) * 64.0f) << 16);
            __stcs(&((uint32_t*)g_x8l)[i], l);
        }
    }
}

// ---------------- fused persistent GEMM ---------------------------------------
#define NPAIR    74
#define NTHR     288
#define SST      73728
#define OF_AH    0
#define OF_B0    16384
#define OF_B1    32768
#define OF_AL    49152
#define OF_B0L   57344
#define OF_B1L   65536
#define GSMEM    (3 * SST + 1024)

#define K1_NC    (KD / 64)               // 64
#define K1_NT    (KI / 256)              // 43
#define K1_GM    16
#define K1_TILES (K1_NT * (KM / 256))    // 1376
#define K2_NC    (KI / 64)               // 172
#define K2_NT    (KD / 512)              // 8
#define K2_GM    8
#define K2_TILES (K2_NT * (KM / 256))    // 256
#define RDY_TGT  (2 * K1_NT)             // 86: both CTAs x 43 n-tiles

extern __shared__ char dsm[];

__global__ void __launch_bounds__(NTHR, 1) __cluster_dims__(2, 1, 1)
kmain(const float* __restrict__ gs_p, const float* __restrict__ us_p,
      const float* __restrict__ ds_p, float* __restrict__ out)
{
#if TC_OK
    const int t = threadIdx.x, wid = t >> 5, lane = t & 31;
    const uint32_t rank = ctarank();
    const int pair = blockIdx.y;
    const uint32_t sb = (smem_u32(dsm) + 1023u) & ~1023u;

    __shared__ uint32_t s_tm[1];
    __shared__ alignas(8) uint64_t s_mb[11];  // full[3], rdy[3], done[3], tdone, epi

    if (wid == 8) TC_ALLOC2(smem_u32(s_tm), 512);
    if (t == 0) {
#pragma unroll
        for (int i = 0; i < 3; ++i) {
            MBAR_INIT(smem_u32(&s_mb[i]),     128);
            MBAR_INIT(smem_u32(&s_mb[3 + i]), 2);
            MBAR_INIT(smem_u32(&s_mb[6 + i]), 1);
        }
        MBAR_INIT(smem_u32(&s_mb[9]),  1);
        MBAR_INIT(smem_u32(&s_mb[10]), 2);
    }
    __syncthreads();
    CLUSTER_SYNC();
    uint32_t tm;
    asm volatile("ld.shared.b32 %0, [%1];" : "=r"(tm) : "r"(smem_u32(s_tm)));
    const uint32_t full0 = smem_u32(&s_mb[0]), rdy0 = smem_u32(&s_mb[3]);
    const uint32_t done0 = smem_u32(&s_mb[6]);
    const uint32_t tdone = smem_u32(&s_mb[9]), epib = smem_u32(&s_mb[10]);

    if (t >= 128 && t < 256) {
        // =============== producers (q continues across phases) ===============
        const int tp  = t - 128;
        const int c16 = tp & 7;
        const int r0  = tp >> 3;
        const uint32_t swc = (uint32_t)((c16 ^ (r0 & 7)) * 16);
        const int c4  = tp & 3;
        const int r4  = tp >> 2;
        long q = 0;
        for (int idx = pair; idx < K1_TILES; idx += NPAIR) {      // ---- k1 ----
            const int band = idx / (K1_NT * K1_GM);
            const int rsub = idx % (K1_NT * K1_GM);
            const int n0   = (rsub / K1_GM) * 256;
            const int mp   = band * K1_GM + rsub % K1_GM;
            const int m0   = (mp * 2 + (int)rank) * 128;
            const __nv_bfloat16* pxh = g_xh + (size_t)(m0 + r0) * KD + c16 * 8;
            const __nv_bfloat16* pg  = g_wg + (size_t)(n0 + rank * 128 + r0) * KD + c16 * 8;
            const __nv_bfloat16* pu  = g_wu + (size_t)(n0 + rank * 128 + r0) * KD + c16 * 8;
            const unsigned char* pxl = g_x8l + (size_t)(m0 + r4) * KD + c4 * 16;
            const unsigned char* pg8 = g_w8g + (size_t)(n0 + rank * 128 + r4) * KD + c4 * 16;
            const unsigned char* pu8 = g_w8u + (size_t)(n0 + rank * 128 + r4) * KD + c4 * 16;
            for (int c = 0; c < K1_NC; ++c, ++q) {
                const int s = (int)(q % 3);
                if (q >= 3) MBAR_WAIT(done0 + s * 8, (int)((q / 3 - 1) & 1));
                const int k0 = c * 64;
                const uint32_t st = sb + s * SST;
#pragma unroll
                for (int i = 0; i < 8; ++i) {
                    const uint32_t d = (uint32_t)((r0 + 16 * i) * 128) + swc;
                    const size_t go = (size_t)(16 * i) * KD + k0;
                    cp16(st + OF_AH + d, pxh + go);
                    cp16(st + OF_B0 + d, pg + go);
                    cp16(st + OF_B1 + d, pu + go);
                }
#pragma unroll
                for (int i = 0; i < 4; ++i) {
                    const uint32_t o = (uint32_t)((r4 + 32 * i) * 64 + c4 * 16);
                    const uint32_t d = sw64(o);
                    const size_t go = (size_t)(32 * i) * KD + k0;
                    cp16(st + OF_AL  + d, pxl + go);
                    cp16(st + OF_B0L + d, pg8 + go);
                    cp16(st + OF_B1L + d, pu8 + go);
                }
                CP_MBAR_ARRIVE(full0 + s * 8);
            }
        }
        for (int idx = pair; idx < K2_TILES; idx += NPAIR) {      // ---- k2 ----
            const int band = idx / (K2_NT * K2_GM);
            const int rsub = idx % (K2_NT * K2_GM);
            const int n0   = (rsub / K2_GM) * 512;
            const int mp   = band * K2_GM + rsub % K2_GM;
            const int m0   = (mp * 2 + (int)rank) * 128;
            while (rdy_acquire(&g_rdy[mp]) < RDY_TGT) __nanosleep(128);
            const __nv_bfloat16* pah = g_hh + (size_t)(m0 + r0) * KI + c16 * 8;
            const __nv_bfloat16* pb0 = g_wd + (size_t)(n0 +       rank * 128 + r0) * KI + c16 * 8;
            const __nv_bfloat16* pb1 = g_wd + (size_t)(n0 + 256 + rank * 128 + r0) * KI + c16 * 8;
            const unsigned char* pal = g_h8l + (size_t)(m0 + r4) * KI + c4 * 16;
            const unsigned char* p08 = g_w8d + (size_t)(n0 +       rank * 128 + r4) * KI + c4 * 16;
            const unsigned char* p18 = g_w8d + (size_t)(n0 + 256 + rank * 128 + r4) * KI + c4 * 16;
            for (int c = 0; c < K2_NC; ++c, ++q) {
                const int s = (int)(q % 3);
                if (q >= 3) MBAR_WAIT(done0 + s * 8, (int)((q / 3 - 1) & 1));
                const int k0 = c * 64;
                const uint32_t st = sb + s * SST;
#pragma unroll
                for (int i = 0; i < 8; ++i) {
                    const uint32_t d = (uint32_t)((r0 + 16 * i) * 128) + swc;
                    const size_t go = (size_t)(16 * i) * KI + k0;
                    cp16(st + OF_AH + d, pah + go);
                    cp16(st + OF_B0 + d, pb0 + go);
                    cp16(st + OF_B1 + d, pb1 + go);
                }
#pragma unroll
                for (int i = 0; i < 4; ++i) {
                    const uint32_t o = (uint32_t)((r4 + 32 * i) * 64 + c4 * 16);
                    const uint32_t d = sw64(o);
                    const size_t go = (size_t)(32 * i) * KI + k0;
                    cp16(st + OF_AL  + d, pal + go);
                    cp16(st + OF_B0L + d, p08 + go);
                    cp16(st + OF_B1L + d, p18 + go);
                }
                CP_MBAR_ARRIVE(full0 + s * 8);
            }
        }
    } else if (t == 257) {
        // =============== relay ===============
        long q = 0;
        for (int idx = pair; idx < K1_TILES; idx += NPAIR)
            for (int c = 0; c < K1_NC; ++c, ++q) {
                const int s = (int)(q % 3);
                MBAR_WAIT(full0 + s * 8, (int)((q / 3) & 1));
                FENCE_ASYNC();
                mbar_arrive_cluster(rdy0 + s * 8, 0);
            }
        for (int idx = pair; idx < K2_TILES; idx += NPAIR)
            for (int c = 0; c < K2_NC; ++c, ++q) {
                const int s = (int)(q % 3);
                MBAR_WAIT(full0 + s * 8, (int)((q / 3) & 1));
                FENCE_ASYNC();
                mbar_arrive_cluster(rdy0 + s * 8, 0);
            }
    } else if (rank == 0 && t == 256) {
        // =============== MMA leader ===============
        long q = 0; int it = 0;
        for (int idx = pair; idx < K1_TILES; idx += NPAIR, ++it) {
            if (it > 0) MBAR_WAIT_CL(epib, (it - 1) & 1);
            for (int c = 0; c < K1_NC; ++c, ++q) {
                const int s = (int)(q % 3);
                MBAR_WAIT_CL(rdy0 + s * 8, (int)((q / 3) & 1));
                const uint32_t st = sb + s * SST;
                const uint64_t da = sdesc(st + OF_AH);
                const uint64_t dg = sdesc(st + OF_B0), du = sdesc(st + OF_B1);
                const uint64_t dal = sdesc64(st + OF_AL);
                const uint64_t dgl = sdesc64(st + OF_B0L), dul = sdesc64(st + OF_B1L);
#pragma unroll
                for (int k = 0; k < 4; ++k) {
                    const bool acc = (c > 0) || (k > 0);
                    mma2(tm,       da + 2 * k, dg + 2 * k, IDESC2, acc);
                    mma2(tm + 256, da + 2 * k, du + 2 * k, IDESC2, acc);
                }
#pragma unroll
                for (int k = 0; k < 2; ++k) {
                    mma2_f8(tm,       dal + 2 * k, dgl + 2 * k, IDESC2_F8);
                    mma2_f8(tm + 256, dal + 2 * k, dul + 2 * k, IDESC2_F8);
                }
                TC_COMMIT_MC2(done0 + s * 8, 0x3);
                if (c == K1_NC - 1) TC_COMMIT_MC2(tdone, 0x3);
            }
        }
        for (int idx = pair; idx < K2_TILES; idx += NPAIR, ++it) {
            MBAR_WAIT_CL(epib, (it - 1) & 1);       // it >= 1 always here
            for (int c = 0; c < K2_NC; ++c, ++q) {
                const int s = (int)(q % 3);
                MBAR_WAIT_CL(rdy0 + s * 8, (int)((q / 3) & 1));
                const uint32_t st = sb + s * SST;
                const uint64_t da = sdesc(st + OF_AH);
                const uint64_t d0 = sdesc(st + OF_B0), d1 = sdesc(st + OF_B1);
                const uint64_t dal = sdesc64(st + OF_AL);
                const uint64_t d0l = sdesc64(st + OF_B0L), d1l = sdesc64(st + OF_B1L);
#pragma unroll
                for (int k = 0; k < 4; ++k) {
                    const bool acc = (c > 0) || (k > 0);
                    mma2(tm,       da + 2 * k, d0 + 2 * k, IDESC2, acc);
                    mma2(tm + 256, da + 2 * k, d1 + 2 * k, IDESC2, acc);
                }
#pragma unroll
                for (int k = 0; k < 2; ++k) {
                    mma2_f8(tm,       dal + 2 * k, d0l + 2 * k, IDESC2_F8);
                    mma2_f8(tm + 256, dal + 2 * k, d1l + 2 * k, IDESC2_F8);
                }
                TC_COMMIT_MC2(done0 + s * 8, 0x3);
                if (c == K2_NC - 1) TC_COMMIT_MC2(tdone, 0x3);
            }
        }
    } else if (t < 128) {
        // =============== consumers (it continues across phases) ===============
        const float gsc = gs_p[0], usc = us_p[0], dsc = ds_p[0];
        int it = 0;
        for (int idx = pair; idx < K1_TILES; idx += NPAIR, ++it) {  // ---- k1 ----
            const int band = idx / (K1_NT * K1_GM);
            const int rsub = idx % (K1_NT * K1_GM);
            const int n0   = (rsub / K1_GM) * 256;
            const int mp   = band * K1_GM + rsub % K1_GM;
            const int m0   = (mp * 2 + (int)rank) * 128;
            MBAR_WAIT(tdone, it & 1);
            TC_FENCE_AFTER();
            const int m = m0 + wid * 32 + lane;
#pragma unroll 1
            for (int cb = 0; cb < 8; ++cb) {
                uint32_t rg[32], ru[32];
                LDTM32(rg, tm + cb * 32);
                LDTM32(ru, tm + 256 + cb * 32);
                TC_WAIT_LD();
                alignas(16) ushort oh[32];
                alignas(16) unsigned char ol8[32];
#pragma unroll
                for (int j = 0; j < 32; ++j) {
                    const float g = __uint_as_float(rg[j]) * gsc;
                    const float u = __uint_as_float(ru[j]) * usc;
                    const float v = (g / (1.0f + __expf(-g))) * u;
                    const __nv_bfloat16 hh = __float2bfloat16(v);
                    oh[j] = *(const ushort*)&hh;
                    ol8[j] = __nv_fp8_e4m3((v - __bfloat162float(hh)) * 2.0f).__x;
                }
                const size_t eoff = (size_t)m * KI + n0 + cb * 32;
#pragma unroll
                for (int qq = 0; qq < 4; ++qq)
                    *(uint4*)((char*)g_hh + eoff * 2 + qq * 16) = *(uint4*)&oh[qq * 8];
#pragma unroll
                for (int qq = 0; qq < 2; ++qq)
                    *(uint4*)(g_h8l + eoff + qq * 16) = *(uint4*)&ol8[qq * 16];
            }
            TC_FENCE_BEFORE();
            asm volatile("bar.sync 1, 128;" ::: "memory");
            if (t == 0) {
                mbar_arrive_cluster(epib, 0);
                rdy_release(&g_rdy[mp]);            // publish h for this CTA
            }
        }
        for (int idx = pair; idx < K2_TILES; idx += NPAIR, ++it) {  // ---- k2 ----
            const int band = idx / (K2_NT * K2_GM);
            const int rsub = idx % (K2_NT * K2_GM);
            const int n0   = (rsub / K2_GM) * 512;
            const int mp   = band * K2_GM + rsub % K2_GM;
            const int m0   = (mp * 2 + (int)rank) * 128;
            MBAR_WAIT(tdone, it & 1);
            TC_FENCE_AFTER();
            const int m = m0 + wid * 32 + lane;
#pragma unroll 1
            for (int cb = 0; cb < 16; ++cb) {
                uint32_t r[32];
                LDTM32(r, tm + cb * 32);
                TC_WAIT_LD();
                float* p = out + (size_t)m * KD + n0 + cb * 32;
#pragma unroll
                for (int qq = 0; qq < 8; ++qq) {
                    float4 v;
                    v.x = __uint_as_float(r[qq * 4 + 0]) * dsc;
                    v.y = __uint_as_float(r[qq * 4 + 1]) * dsc;
                    v.z = __uint_as_float(r[qq * 4 + 2]) * dsc;
                    v.w = __uint_as_float(r[qq * 4 + 3]) * dsc;
                    *(float4*)(p + qq * 4) = v;
                }
            }
            TC_FENCE_BEFORE();
            asm volatile("bar.sync 1, 128;" ::: "memory");
            if (t == 0) mbar_arrive_cluster(epib, 0);
        }
    }
    __syncthreads();
    if (wid == 8) { TC_RELINQ2(); TC_DEALLOC2(tm, 512); }
    CLUSTER_SYNC();

#else  // ---------------- SIMT fallback (compile-only; never runs on GB300) ----
    const int t = threadIdx.x;
    const float gsc = gs_p[0], usc = us_p[0], dsc = ds_p[0];
    for (int idx = blockIdx.y; idx < K1_TILES; idx += NPAIR) {
        const int band = idx / (K1_NT * K1_GM);
        const int rsub = idx % (K1_NT * K1_GM);
        const int n0   = (rsub / K1_GM) * 256;
        const int mp   = band * K1_GM + rsub % K1_GM;
        const int m0   = (mp * 2 + blockIdx.x) * 128;
        for (int e = t; e < 128 * 256; e += blockDim.x) {
            const int r = e >> 8, col = e & 255;
            const int m = m0 + r;
            float ag = 0.f, au = 0.f;
            for (int k = 0; k < KD; ++k) {
                const float xv = __bfloat162float(g_xh[(size_t)m * KD + k]);
                ag += xv * __bfloat162float(g_wg[(size_t)(n0 + col) * KD + k]);
                au += xv * __bfloat162float(g_wu[(size_t)(n0 + col) * KD + k]);
            }
            const float g = ag * gsc;
            const float v = (g / (1.0f + __expf(-g))) * (au * usc);
            const __nv_bfloat16 hh = __float2bfloat16(v);
            g_hh[(size_t)m * KI + n0 + col] = hh;
            g_h8l[(size_t)m * KI + n0 + col] =
                __nv_fp8_e4m3((v - __bfloat162float(hh)) * 2.0f).__x;
        }
        __syncthreads();
        if (t == 0) atomicAdd(&g_rdy[mp], 2);
    }
    for (int idx = blockIdx.y; idx < K2_TILES; idx += NPAIR) {
        const int band = idx / (K2_NT * K2_GM);
        const int rsub = idx % (K2_NT * K2_GM);
        const int n0   = (rsub / K2_GM) * 512;
        const int mp   = band * K2_GM + rsub % K2_GM;
        const int m0   = (mp * 2 + blockIdx.x) * 128;
        if (t == 0) while (atomicAdd(&g_rdy[mp], 0) < RDY_TGT) {}
        __syncthreads();
        for (int e = t; e < 128 * 512; e += blockDim.x) {
            const int r = e >> 9, col = e & 511;
            const int m = m0 + r;
            float acc = 0.f;
            for (int k = 0; k < KI; ++k)
                acc += __bfloat162float(g_hh[(size_t)m * KI + k])
                     * __bfloat162float(g_wd[(size_t)(n0 + col) * KI + k]);
            out[(size_t)m * KD + n0 + col] = acc * dsc;
        }
    }
#endif
}

// ---------------- launch ------------------------------------------------------
extern "C" void kernel_launch(void* const* d_in, const int* in_sizes, int n_in,
                              void* d_out, int out_size)
{
    const float* x  = (const float*)d_in[0];
    const int*   gw = (const int*)  d_in[1];
    const float* gs = (const float*)d_in[2];
    const int*   uw = (const int*)  d_in[3];
    const float* us = (const float*)d_in[4];
    const int*   dw = (const int*)  d_in[5];
    const float* ds = (const float*)d_in[6];
    float* out = (float*)d_out;

    cudaFuncSetAttribute(kmain, cudaFuncAttributeMaxDynamicSharedMemorySize, GSMEM);

    prep<<<PREP_NB, 256>>>(gw, uw, dw, x);
    kmain<<<dim3(2, NPAIR, 1), NTHR, GSMEM>>>(gs, us, ds, out);
}

// round 16
// speedup vs baseline: 1.4546x; 1.0153x over previous
#include <cuda_runtime.h>
#include <cuda_bf16.h>
#include <cuda_fp8.h>
#include <cstdint>
#include <math.h>

#define KD 4096
#define KI 11008
#define KM 8192

#if !defined(__CUDA_ARCH__) || defined(__CUDA_ARCH_FEAT_SM103_ALL)
#define TC_OK 1
#else
#define TC_OK 0
#endif

// ---------------- persistent scratch (__device__ globals; no allocs) -------
__device__ __nv_bfloat16 g_wg[(size_t)KI * KD];   // gate w bf16 [I,D]
__device__ __nv_bfloat16 g_wu[(size_t)KI * KD];   // up   w bf16 [I,D]
__device__ __nv_bfloat16 g_wd[(size_t)KD * KI];   // down w bf16 [D,I]
__device__ unsigned char g_w8g[(size_t)KI * KD];  // e4m3(gate/64)
__device__ unsigned char g_w8u[(size_t)KI * KD];  // e4m3(up/64)
__device__ unsigned char g_w8d[(size_t)KD * KI];  // e4m3(down/2)
__device__ __nv_bfloat16 g_xh[(size_t)KM * KD];   // x hi bf16
__device__ unsigned char g_x8l[(size_t)KM * KD];  // e4m3((x-xh)*64)
__device__ __nv_bfloat16 g_hh[(size_t)KM * KI];   // h hi bf16
__device__ unsigned char g_h8l[(size_t)KM * KI];  // e4m3((h-hh)*2)
__device__ int           g_rdy[KM / 256];         // per-m-pair readiness (0..86)

// ---------------- PTX helpers ----------------------------------------------
__device__ __forceinline__ uint32_t smem_u32(const void* p) {
    return (uint32_t)__cvta_generic_to_shared(p);
}
__device__ __forceinline__ void cp16(uint32_t dst, const void* src) {
    asm volatile("cp.async.cg.shared.global [%0], [%1], 16;" :: "r"(dst), "l"(src));
}
__device__ __forceinline__ uint32_t bf16x2_of(float lo, float hi) {
    uint32_t r;
    asm("cvt.rn.bf16x2.f32 %0, %1, %2;" : "=r"(r) : "f"(hi), "f"(lo));
    return r;
}
__device__ __forceinline__ uint32_t e4m3x2_of(float lo, float hi) {
    uint16_t r;
    asm("cvt.rn.satfinite.e4m3x2.f32 %0, %1, %2;" : "=h"(r) : "f"(hi), "f"(lo));
    return (uint32_t)r;
}

#if TC_OK
__device__ __forceinline__ uint32_t ctarank() {
    uint32_t r; asm("mov.u32 %0, %%cluster_ctarank;" : "=r"(r)); return r;
}

#define CP_MBAR_ARRIVE(mb) \
    asm volatile("cp.async.mbarrier.arrive.noinc.shared::cta.b64 [%0];" :: "r"(mb) : "memory")

#define TC_ALLOC2(sa, n)  asm volatile("tcgen05.alloc.cta_group::2.sync.aligned.shared::cta.b32 [%0], %1;" :: "r"(sa), "r"(n) : "memory")
#define TC_DEALLOC2(t, n) asm volatile("tcgen05.dealloc.cta_group::2.sync.aligned.b32 %0, %1;" :: "r"(t), "r"(n))
#define TC_RELINQ2()      asm volatile("tcgen05.relinquish_alloc_permit.cta_group::2.sync.aligned;")
#define TC_COMMIT_MC2(mb, mask) asm volatile("tcgen05.commit.cta_group::2.mbarrier::arrive::one.shared::cluster.multicast::cluster.b64 [%0], %1;" :: "r"(mb), "h"((uint16_t)(mask)) : "memory")
#define TC_WAIT_LD()      asm volatile("tcgen05.wait::ld.sync.aligned;" ::: "memory")
#define TC_FENCE_AFTER()  asm volatile("tcgen05.fence::after_thread_sync;" ::: "memory")
#define TC_FENCE_BEFORE() asm volatile("tcgen05.fence::before_thread_sync;" ::: "memory")
#define FENCE_ASYNC()     asm volatile("fence.proxy.async.shared::cta;" ::: "memory")
#define MBAR_INIT(a, c)   asm volatile("mbarrier.init.shared.b64 [%0], %1;" :: "r"(a), "r"(c) : "memory")
#define CLUSTER_SYNC() do { \
    asm volatile("barrier.cluster.arrive.aligned;" ::: "memory"); \
    asm volatile("barrier.cluster.wait.aligned;"   ::: "memory"); } while (0)

__device__ __forceinline__ void mbar_arrive_cluster(uint32_t addr, uint32_t rank) {
    asm volatile("{\n\t.reg .b32 ra;\n\tmapa.shared::cluster.u32 ra, %0, %1;\n\t"
                 "mbarrier.arrive.shared::cluster.b64 _, [ra];\n\t}"
                 :: "r"(addr), "r"(rank) : "memory");
}
__device__ __forceinline__ void rdy_release(int* p) {
    asm volatile("red.release.gpu.global.add.s32 [%0], 1;" :: "l"(p) : "memory");
}
__device__ __forceinline__ int rdy_acquire(const int* p) {
    int v;
    asm volatile("ld.acquire.gpu.global.b32 %0, [%1];" : "=r"(v) : "l"(p) : "memory");
    return v;
}

#define MBAR_WAIT(mb, ph) do {                                                    \
    uint32_t _m = (mb), _p = (uint32_t)(ph), _d;                                  \
    asm volatile("{\n\t.reg .pred p;\n\t"                                         \
        "mbarrier.try_wait.parity.acquire.cta.shared::cta.b64 p, [%1], %2;\n\t"   \
        "selp.b32 %0, 1, 0, p;\n\t}" : "=r"(_d) : "r"(_m), "r"(_p) : "memory");   \
    if (!_d) {                                                                    \
        asm volatile("{\n\t.reg .pred P1;\n\tWL_%=:\n\t"                          \
            "mbarrier.try_wait.parity.acquire.cta.shared::cta.b64 P1, [%0], %1, 0x989680;\n\t" \
            "@P1 bra.uni WD_%=;\n\tbra.uni WL_%=;\n\tWD_%=:\n\t}"                 \
            :: "r"(_m), "r"(_p) : "memory");                                      \
    }                                                                             \
} while (0)

#define MBAR_WAIT_CL(mb, ph) do {                                                 \
    uint32_t _m = (mb), _p = (uint32_t)(ph), _d;                                  \
    asm volatile("{\n\t.reg .pred p;\n\t"                                         \
        "mbarrier.try_wait.parity.acquire.cluster.shared::cta.b64 p, [%1], %2;\n\t" \
        "selp.b32 %0, 1, 0, p;\n\t}" : "=r"(_d) : "r"(_m), "r"(_p) : "memory");   \
    if (!_d) {                                                                    \
        asm volatile("{\n\t.reg .pred P1;\n\tWL_%=:\n\t"                          \
            "mbarrier.try_wait.parity.acquire.cluster.shared::cta.b64 P1, [%0], %1, 0x989680;\n\t" \
            "@P1 bra.uni WD_%=;\n\tbra.uni WL_%=;\n\tWD_%=:\n\t}"                 \
            :: "r"(_m), "r"(_p) : "memory");                                      \
    }                                                                             \
} while (0)

#define LDTM32(r, ta)                                                             \
    asm volatile("tcgen05.ld.sync.aligned.32x32b.x32.b32 "                        \
        "{%0,%1,%2,%3,%4,%5,%6,%7,%8,%9,%10,%11,%12,%13,%14,%15,"                 \
        "%16,%17,%18,%19,%20,%21,%22,%23,%24,%25,%26,%27,%28,%29,%30,%31},[%32];" \
        : "=r"((r)[0]),"=r"((r)[1]),"=r"((r)[2]),"=r"((r)[3]),                    \
          "=r"((r)[4]),"=r"((r)[5]),"=r"((r)[6]),"=r"((r)[7]),                    \
          "=r"((r)[8]),"=r"((r)[9]),"=r"((r)[10]),"=r"((r)[11]),                  \
          "=r"((r)[12]),"=r"((r)[13]),"=r"((r)[14]),"=r"((r)[15]),                \
          "=r"((r)[16]),"=r"((r)[17]),"=r"((r)[18]),"=r"((r)[19]),                \
          "=r"((r)[20]),"=r"((r)[21]),"=r"((r)[22]),"=r"((r)[23]),                \
          "=r"((r)[24]),"=r"((r)[25]),"=r"((r)[26]),"=r"((r)[27]),                \
          "=r"((r)[28]),"=r"((r)[29]),"=r"((r)[30]),"=r"((r)[31])                 \
        : "r"(ta))

__device__ __forceinline__ uint64_t sdesc(uint32_t addr) {      // SW128 bf16 tiles
    return 0x4000404000010000ULL | (uint64_t)((addr >> 4) & 0x3FFF);
}
__device__ __forceinline__ uint64_t sdesc64(uint32_t addr) {    // SW64 fp8 tiles
    return (4ull << 61) | (1ull << 46) | (32ull << 32) | (1ull << 16)
         | (uint64_t)((addr >> 4) & 0x3FFF);
}
__device__ __forceinline__ uint32_t sw64(uint32_t o) { return o ^ ((o >> 3) & 0x30); }

__device__ __forceinline__ void mma2(uint32_t d, uint64_t a, uint64_t b,
                                     uint32_t idesc, bool acc) {
    uint32_t en = acc ? 1u : 0u;
    asm volatile("{\n\t.reg .pred p;\n\tsetp.ne.u32 p, %5, 0;\n\t"
        "tcgen05.mma.cta_group::2.kind::f16 [%0], %1, %2, %3, "
        "{%4,%4,%4,%4,%4,%4,%4,%4}, p;\n\t}"
        :: "r"(d), "l"(a), "l"(b), "r"(idesc), "r"(0u), "r"(en) : "memory");
}
__device__ __forceinline__ void mma2_f8(uint32_t d, uint64_t a, uint64_t b,
                                        uint32_t idesc) {
    asm volatile("{\n\t.reg .pred p;\n\tsetp.ne.u32 p, 1, 0;\n\t"
        "tcgen05.mma.cta_group::2.kind::f8f6f4 [%0], %1, %2, %3, "
        "{%4,%4,%4,%4,%4,%4,%4,%4}, p;\n\t}"
        :: "r"(d), "l"(a), "l"(b), "r"(idesc), "r"(0u) : "memory");
}

#define IDESC2    ((1u << 4) | (1u << 7) | (1u << 10) | ((256u / 8) << 17) | ((256u / 16) << 24))
#define IDESC2_F8 ((1u << 4) | ((256u / 8) << 17) | ((256u / 16) << 24))
#endif // TC_OK

// ---------------- fused pre-pass (static block partition, packed cvt) --------
#define PREP_WB   1280
#define PREP_XB   256
#define PREP_NB   (3 * PREP_WB + PREP_XB)

__global__ void __launch_bounds__(256) prep(const int* __restrict__ gw,
                                            const int* __restrict__ uw,
                                            const int* __restrict__ dw,
                                            const float* __restrict__ x) {
    const int b = blockIdx.x;
    if (b == 0 && threadIdx.x < KM / 256) g_rdy[threadIdx.x] = 0;  // reset handoff
    if (b < 3 * PREP_WB) {
        const int sel = b / PREP_WB;
        const int rb  = b - sel * PREP_WB;
        const int* __restrict__ w = (sel == 0) ? gw : (sel == 1) ? uw : dw;
        __nv_bfloat16* o  = (sel == 0) ? g_wg : (sel == 1) ? g_wu : g_wd;
        unsigned char* o8 = (sel == 0) ? g_w8g : (sel == 1) ? g_w8u : g_w8d;
        const float sc8 = (sel == 2) ? 0.5f : (1.0f / 64.0f);
        const long n4 = (long)KI * KD / 4;
        const long step = (long)PREP_WB * 256;
        for (long j = (long)rb * 256 + threadIdx.x; j < n4; j += step) {
            const int4 v = __ldcs(&((const int4*)w)[j]);
            const float f0 = (float)v.x, f1 = (float)v.y;
            const float f2 = (float)v.z, f3 = (float)v.w;
            uint2 pb;
            pb.x = bf16x2_of(f0, f1);
            pb.y = bf16x2_of(f2, f3);
            __stcs(&((uint2*)o)[j], pb);
            const uint32_t q = e4m3x2_of(f0 * sc8, f1 * sc8)
                             | (e4m3x2_of(f2 * sc8, f3 * sc8) << 16);
            __stcs(&((uint32_t*)o8)[j], q);
        }
    } else {
        const int rb = b - 3 * PREP_WB;
        const long x4 = (long)KM * KD / 4;
        const long step = (long)PREP_XB * 256;
        for (long i = (long)rb * 256 + threadIdx.x; i < x4; i += step) {
            const float4 v = __ldcs(&((const float4*)x)[i]);
            const uint32_t h01 = bf16x2_of(v.x, v.y);
            const uint32_t h23 = bf16x2_of(v.z, v.w);
            const float a0 = __uint_as_float(h01 << 16);
            const float a1 = __uint_as_float(h01 & 0xFFFF0000u);
            const float a2 = __uint_as_float(h23 << 16);
            const float a3 = __uint_as_float(h23 & 0xFFFF0000u);
            uint2 ph; ph.x = h01; ph.y = h23;
            __stcs(&((uint2*)g_xh)[i], ph);
            const uint32_t l = e4m3x2_of((v.x - a0) * 64.0f, (v.y - a1) * 64.0f)
                             | (e4m3x2_of((v.z - a2) * 64.0f, (v.w - a3) * 64.0f) << 16);
            __stcs(&((uint32_t*)g_x8l)[i], l);
        }
    }
}

// ---------------- fused persistent GEMM ---------------------------------------
#define NPAIR    74
#define NTHR     288
#define SST      73728
#define OF_AH    0
#define OF_B0    16384
#define OF_B1    32768
#define OF_AL    49152
#define OF_B0L   57344
#define OF_B1L   65536
#define GSMEM    (3 * SST + 1024)

#define K1_NC    (KD / 64)               // 64
#define K1_NT    (KI / 256)              // 43
#define K1_GM    16
#define K1_TILES (K1_NT * (KM / 256))    // 1376
#define K2_NC    (KI / 64)               // 172
#define K2_NT    (KD / 512)              // 8
#define K2_GM    8
#define K2_TILES (K2_NT * (KM / 256))    // 256
#define RDY_TGT  (2 * K1_NT)             // 86

// ---- jointly balanced schedule: per-pair chunk loads within 0.7% of ideal ----
// pairs 0..33:  17 k1 + 4 k2 = 1776 chunks
// pairs 34..71: 20 k1 + 3 k2 = 1796
// pairs 72..73: 19 k1 + 3 k2 = 1732
__device__ __forceinline__ int k1_tile(int pair, int r) {
    if (r < 17) return r * NPAIR + pair;
    if (pair < 34) return -1;
    if (r == 17) return 17 * NPAIR + (pair - 34);               // 1258..1297
    if (r == 18) return 17 * NPAIR + 40 + (pair - 34);          // 1298..1337
    return (pair < 72) ? 17 * NPAIR + 80 + (pair - 34) : -1;    // 1338..1375
}
__device__ __forceinline__ int k2_tile(int pair, int r) {
    if (r < 3) return r * NPAIR + pair;                         // 0..221
    return (pair < 34) ? 3 * NPAIR + pair : -1;                 // 222..255
}
#define K1_ROUNDS 20
#define K2_ROUNDS 4

extern __shared__ char dsm[];

#if TC_OK
__global__ void __launch_bounds__(NTHR, 1) __cluster_dims__(2, 1, 1)
kmain(const float* __restrict__ gs_p, const float* __restrict__ us_p,
      const float* __restrict__ ds_p, float* __restrict__ out)
{
    const int t = threadIdx.x, wid = t >> 5, lane = t & 31;
    const uint32_t rank = ctarank();
    const int pair = blockIdx.y;
    const uint32_t sb = (smem_u32(dsm) + 1023u) & ~1023u;

    __shared__ uint32_t s_tm[1];
    __shared__ alignas(8) uint64_t s_mb[11];  // full[3], rdy[3], done[3], tdone, epi

    if (wid == 8) TC_ALLOC2(smem_u32(s_tm), 512);
    if (t == 0) {
#pragma unroll
        for (int i = 0; i < 3; ++i) {
            MBAR_INIT(smem_u32(&s_mb[i]),     128);
            MBAR_INIT(smem_u32(&s_mb[3 + i]), 2);
            MBAR_INIT(smem_u32(&s_mb[6 + i]), 1);
        }
        MBAR_INIT(smem_u32(&s_mb[9]),  1);
        MBAR_INIT(smem_u32(&s_mb[10]), 2);
    }
    __syncthreads();
    CLUSTER_SYNC();
    uint32_t tm;
    asm volatile("ld.shared.b32 %0, [%1];" : "=r"(tm) : "r"(smem_u32(s_tm)));
    const uint32_t full0 = smem_u32(&s_mb[0]), rdy0 = smem_u32(&s_mb[3]);
    const uint32_t done0 = smem_u32(&s_mb[6]);
    const uint32_t tdone = smem_u32(&s_mb[9]), epib = smem_u32(&s_mb[10]);

    if (t >= 128 && t < 256) {
        // =============== producers ===============
        const int tp  = t - 128;
        const int c16 = tp & 7;
        const int r0  = tp >> 3;
        const uint32_t swc = (uint32_t)((c16 ^ (r0 & 7)) * 16);
        const int c4  = tp & 3;
        const int r4  = tp >> 2;
        long q = 0;
        for (int rr = 0; rr < K1_ROUNDS; ++rr) {                  // ---- k1 ----
            const int idx = k1_tile(pair, rr);
            if (idx < 0) continue;
            const int band = idx / (K1_NT * K1_GM);
            const int rsub = idx % (K1_NT * K1_GM);
            const int n0   = (rsub / K1_GM) * 256;
            const int mp   = band * K1_GM + rsub % K1_GM;
            const int m0   = (mp * 2 + (int)rank) * 128;
            const __nv_bfloat16* pxh = g_xh + (size_t)(m0 + r0) * KD + c16 * 8;
            const __nv_bfloat16* pg  = g_wg + (size_t)(n0 + rank * 128 + r0) * KD + c16 * 8;
            const __nv_bfloat16* pu  = g_wu + (size_t)(n0 + rank * 128 + r0) * KD + c16 * 8;
            const unsigned char* pxl = g_x8l + (size_t)(m0 + r4) * KD + c4 * 16;
            const unsigned char* pg8 = g_w8g + (size_t)(n0 + rank * 128 + r4) * KD + c4 * 16;
            const unsigned char* pu8 = g_w8u + (size_t)(n0 + rank * 128 + r4) * KD + c4 * 16;
            for (int c = 0; c < K1_NC; ++c, ++q) {
                const int s = (int)(q % 3);
                if (q >= 3) MBAR_WAIT(done0 + s * 8, (int)((q / 3 - 1) & 1));
                const int k0 = c * 64;
                const uint32_t st = sb + s * SST;
#pragma unroll
                for (int i = 0; i < 8; ++i) {
                    const uint32_t d = (uint32_t)((r0 + 16 * i) * 128) + swc;
                    const size_t go = (size_t)(16 * i) * KD + k0;
                    cp16(st + OF_AH + d, pxh + go);
                    cp16(st + OF_B0 + d, pg + go);
                    cp16(st + OF_B1 + d, pu + go);
                }
#pragma unroll
                for (int i = 0; i < 4; ++i) {
                    const uint32_t o = (uint32_t)((r4 + 32 * i) * 64 + c4 * 16);
                    const uint32_t d = sw64(o);
                    const size_t go = (size_t)(32 * i) * KD + k0;
                    cp16(st + OF_AL  + d, pxl + go);
                    cp16(st + OF_B0L + d, pg8 + go);
                    cp16(st + OF_B1L + d, pu8 + go);
                }
                CP_MBAR_ARRIVE(full0 + s * 8);
            }
        }
        for (int rr = 0; rr < K2_ROUNDS; ++rr) {                  // ---- k2 ----
            const int idx = k2_tile(pair, rr);
            if (idx < 0) continue;
            const int band = idx / (K2_NT * K2_GM);
            const int rsub = idx % (K2_NT * K2_GM);
            const int n0   = (rsub / K2_GM) * 512;
            const int mp   = band * K2_GM + rsub % K2_GM;
            const int m0   = (mp * 2 + (int)rank) * 128;
            while (rdy_acquire(&g_rdy[mp]) < RDY_TGT) __nanosleep(128);
            const __nv_bfloat16* pah = g_hh + (size_t)(m0 + r0) * KI + c16 * 8;
            const __nv_bfloat16* pb0 = g_wd + (size_t)(n0 +       rank * 128 + r0) * KI + c16 * 8;
            const __nv_bfloat16* pb1 = g_wd + (size_t)(n0 + 256 + rank * 128 + r0) * KI + c16 * 8;
            const unsigned char* pal = g_h8l + (size_t)(m0 + r4) * KI + c4 * 16;
            const unsigned char* p08 = g_w8d + (size_t)(n0 +       rank * 128 + r4) * KI + c4 * 16;
            const unsigned char* p18 = g_w8d + (size_t)(n0 + 256 + rank * 128 + r4) * KI + c4 * 16;
            for (int c = 0; c < K2_NC; ++c, ++q) {
                const int s = (int)(q % 3);
                if (q >= 3) MBAR_WAIT(done0 + s * 8, (int)((q / 3 - 1) & 1));
                const int k0 = c * 64;
                const uint32_t st = sb + s * SST;
#pragma unroll
                for (int i = 0; i < 8; ++i) {
                    const uint32_t d = (uint32_t)((r0 + 16 * i) * 128) + swc;
                    const size_t go = (size_t)(16 * i) * KI + k0;
                    cp16(st + OF_AH + d, pah + go);
                    cp16(st + OF_B0 + d, pb0 + go);
                    cp16(st + OF_B1 + d, pb1 + go);
                }
#pragma unroll
                for (int i = 0; i < 4; ++i) {
                    const uint32_t o = (uint32_t)((r4 + 32 * i) * 64 + c4 * 16);
                    const uint32_t d = sw64(o);
                    const size_t go = (size_t)(32 * i) * KI + k0;
                    cp16(st + OF_AL  + d, pal + go);
                    cp16(st + OF_B0L + d, p08 + go);
                    cp16(st + OF_B1L + d, p18 + go);
                }
                CP_MBAR_ARRIVE(full0 + s * 8);
            }
        }
    } else if (t == 257) {
        // =============== relay ===============
        long q = 0;
        for (int rr = 0; rr < K1_ROUNDS; ++rr) {
            if (k1_tile(pair, rr) < 0) continue;
            for (int c = 0; c < K1_NC; ++c, ++q) {
                const int s = (int)(q % 3);
                MBAR_WAIT(full0 + s * 8, (int)((q / 3) & 1));
                FENCE_ASYNC();
                mbar_arrive_cluster(rdy0 + s * 8, 0);
            }
        }
        for (int rr = 0; rr < K2_ROUNDS; ++rr) {
            if (k2_tile(pair, rr) < 0) continue;
            for (int c = 0; c < K2_NC; ++c, ++q) {
                const int s = (int)(q % 3);
                MBAR_WAIT(full0 + s * 8, (int)((q / 3) & 1));
                FENCE_ASYNC();
                mbar_arrive_cluster(rdy0 + s * 8, 0);
            }
        }
    } else if (rank == 0 && t == 256) {
        // =============== MMA leader ===============
        long q = 0; int it = 0;
        for (int rr = 0; rr < K1_ROUNDS; ++rr) {
            if (k1_tile(pair, rr) < 0) continue;
            if (it > 0) MBAR_WAIT_CL(epib, (it - 1) & 1);
            for (int c = 0; c < K1_NC; ++c, ++q) {
                const int s = (int)(q % 3);
                MBAR_WAIT_CL(rdy0 + s * 8, (int)((q / 3) & 1));
                const uint32_t st = sb + s * SST;
                const uint64_t da = sdesc(st + OF_AH);
                const uint64_t dg = sdesc(st + OF_B0), du = sdesc(st + OF_B1);
                const uint64_t dal = sdesc64(st + OF_AL);
                const uint64_t dgl = sdesc64(st + OF_B0L), dul = sdesc64(st + OF_B1L);
#pragma unroll
                for (int k = 0; k < 4; ++k) {
                    const bool acc = (c > 0) || (k > 0);
                    mma2(tm,       da + 2 * k, dg + 2 * k, IDESC2, acc);
                    mma2(tm + 256, da + 2 * k, du + 2 * k, IDESC2, acc);
                }
#pragma unroll
                for (int k = 0; k < 2; ++k) {
                    mma2_f8(tm,       dal + 2 * k, dgl + 2 * k, IDESC2_F8);
                    mma2_f8(tm + 256, dal + 2 * k, dul + 2 * k, IDESC2_F8);
                }
                TC_COMMIT_MC2(done0 + s * 8, 0x3);
                if (c == K1_NC - 1) TC_COMMIT_MC2(tdone, 0x3);
            }
            ++it;
        }
        for (int rr = 0; rr < K2_ROUNDS; ++rr) {
            if (k2_tile(pair, rr) < 0) continue;
            MBAR_WAIT_CL(epib, (it - 1) & 1);   // it >= 17 here
            for (int c = 0; c < K2_NC; ++c, ++q) {
                const int s = (int)(q % 3);
                MBAR_WAIT_CL(rdy0 + s * 8, (int)((q / 3) & 1));
                const uint32_t st = sb + s * SST;
                const uint64_t da = sdesc(st + OF_AH);
                const uint64_t d0 = sdesc(st + OF_B0), d1 = sdesc(st + OF_B1);
                const uint64_t dal = sdesc64(st + OF_AL);
                const uint64_t d0l = sdesc64(st + OF_B0L), d1l = sdesc64(st + OF_B1L);
#pragma unroll
                for (int k = 0; k < 4; ++k) {
                    const bool acc = (c > 0) || (k > 0);
                    mma2(tm,       da + 2 * k, d0 + 2 * k, IDESC2, acc);
                    mma2(tm + 256, da + 2 * k, d1 + 2 * k, IDESC2, acc);
                }
#pragma unroll
                for (int k = 0; k < 2; ++k) {
                    mma2_f8(tm,       dal + 2 * k, d0l + 2 * k, IDESC2_F8);
                    mma2_f8(tm + 256, dal + 2 * k, d1l + 2 * k, IDESC2_F8);
                }
                TC_COMMIT_MC2(done0 + s * 8, 0x3);
                if (c == K2_NC - 1) TC_COMMIT_MC2(tdone, 0x3);
            }
            ++it;
        }
    } else if (t < 128) {
        // =============== consumers ===============
        const float gsc = gs_p[0], usc = us_p[0], dsc = ds_p[0];
        int it = 0;
        for (int rr = 0; rr < K1_ROUNDS; ++rr) {                  // ---- k1 ----
            const int idx = k1_tile(pair, rr);
            if (idx < 0) continue;
            const int band = idx / (K1_NT * K1_GM);
            const int rsub = idx % (K1_NT * K1_GM);
            const int n0   = (rsub / K1_GM) * 256;
            const int mp   = band * K1_GM + rsub % K1_GM;
            const int m0   = (mp * 2 + (int)rank) * 128;
            MBAR_WAIT(tdone, it & 1);
            TC_FENCE_AFTER();
            const int m = m0 + wid * 32 + lane;
#pragma unroll 1
            for (int cb = 0; cb < 8; ++cb) {
                uint32_t rg[32], ru[32];
                LDTM32(rg, tm + cb * 32);
                LDTM32(ru, tm + 256 + cb * 32);
                TC_WAIT_LD();
                alignas(16) ushort oh[32];
                alignas(16) unsigned char ol8[32];
#pragma unroll
                for (int j = 0; j < 32; ++j) {
                    const float g = __uint_as_float(rg[j]) * gsc;
                    const float u = __uint_as_float(ru[j]) * usc;
                    const float v = (g / (1.0f + __expf(-g))) * u;
                    const __nv_bfloat16 hh = __float2bfloat16(v);
                    oh[j] = *(const ushort*)&hh;
                    ol8[j] = __nv_fp8_e4m3((v - __bfloat162float(hh)) * 2.0f).__x;
                }
                const size_t eoff = (size_t)m * KI + n0 + cb * 32;
#pragma unroll
                for (int qq = 0; qq < 4; ++qq)
                    *(uint4*)((char*)g_hh + eoff * 2 + qq * 16) = *(uint4*)&oh[qq * 8];
#pragma unroll
                for (int qq = 0; qq < 2; ++qq)
                    *(uint4*)(g_h8l + eoff + qq * 16) = *(uint4*)&ol8[qq * 16];
            }
            TC_FENCE_BEFORE();
            asm volatile("bar.sync 1, 128;" ::: "memory");
            if (t == 0) {
                mbar_arrive_cluster(epib, 0);
                rdy_release(&g_rdy[mp]);
            }
            ++it;
        }
        for (int rr = 0; rr < K2_ROUNDS; ++rr) {                  // ---- k2 ----
            const int idx = k2_tile(pair, rr);
            if (idx < 0) continue;
            const int band = idx / (K2_NT * K2_GM);
            const int rsub = idx % (K2_NT * K2_GM);
            const int n0   = (rsub / K2_GM) * 512;
            const int mp   = band * K2_GM + rsub % K2_GM;
            const int m0   = (mp * 2 + (int)rank) * 128;
            MBAR_WAIT(tdone, it & 1);
            TC_FENCE_AFTER();
            const int m = m0 + wid * 32 + lane;
#pragma unroll 1
            for (int cb = 0; cb < 16; ++cb) {
                uint32_t r[32];
                LDTM32(r, tm + cb * 32);
                TC_WAIT_LD();
                float* p = out + (size_t)m * KD + n0 + cb * 32;
#pragma unroll
                for (int qq = 0; qq < 8; ++qq) {
                    float4 v;
                    v.x = __uint_as_float(r[qq * 4 + 0]) * dsc;
                    v.y = __uint_as_float(r[qq * 4 + 1]) * dsc;
                    v.z = __uint_as_float(r[qq * 4 + 2]) * dsc;
                    v.w = __uint_as_float(r[qq * 4 + 3]) * dsc;
                    *(float4*)(p + qq * 4) = v;
                }
            }
            TC_FENCE_BEFORE();
            asm volatile("bar.sync 1, 128;" ::: "memory");
            if (t == 0) mbar_arrive_cluster(epib, 0);
            ++it;
        }
    }
    __syncthreads();
    if (wid == 8) { TC_RELINQ2(); TC_DEALLOC2(tm, 512); }
    CLUSTER_SYNC();
}

#else  // ---------------- SIMT fallback kmain (compile-only) -------------------
__global__ void __launch_bounds__(NTHR, 1)
kmain(const float* __restrict__ gs_p, const float* __restrict__ us_p,
      const float* __restrict__ ds_p, float* __restrict__ out)
{
    const int t = threadIdx.x;
    const float gsc = gs_p[0], usc = us_p[0], dsc = ds_p[0];
    for (int rr = 0; rr < K1_ROUNDS; ++rr) {
        const int idx = k1_tile(blockIdx.y, rr);
        if (idx < 0) continue;
        const int band = idx / (K1_NT * K1_GM);
        const int rsub = idx % (K1_NT * K1_GM);
        const int n0   = (rsub / K1_GM) * 256;
        const int mp   = band * K1_GM + rsub % K1_GM;
        const int m0   = (mp * 2 + blockIdx.x) * 128;
        for (int e = t; e < 128 * 256; e += blockDim.x) {
            const int r = e >> 8, col = e & 255;
            const int m = m0 + r;
            float ag = 0.f, au = 0.f;
            for (int k = 0; k < KD; ++k) {
                const float xv = __bfloat162float(g_xh[(size_t)m * KD + k]);
                ag += xv * __bfloat162float(g_wg[(size_t)(n0 + col) * KD + k]);
                au += xv * __bfloat162float(g_wu[(size_t)(n0 + col) * KD + k]);
            }
            const float g = ag * gsc;
            const float v = (g / (1.0f + __expf(-g))) * (au * usc);
            const __nv_bfloat16 hh = __float2bfloat16(v);
            g_hh[(size_t)m * KI + n0 + col] = hh;
            g_h8l[(size_t)m * KI + n0 + col] =
                __nv_fp8_e4m3((v - __bfloat162float(hh)) * 2.0f).__x;
        }
        __syncthreads();
        if (t == 0) atomicAdd(&g_rdy[mp], 2);
    }
    for (int rr = 0; rr < K2_ROUNDS; ++rr) {
        const int idx = k2_tile(blockIdx.y, rr);
        if (idx < 0) continue;
        const int band = idx / (K2_NT * K2_GM);
        const int rsub = idx % (K2_NT * K2_GM);
        const int n0   = (rsub / K2_GM) * 512;
        const int mp   = band * K2_GM + rsub % K2_GM;
        const int m0   = (mp * 2 + blockIdx.x) * 128;
        if (t == 0) while (atomicAdd(&g_rdy[mp], 0) < RDY_TGT) {}
        __syncthreads();
        for (int e = t; e < 128 * 512; e += blockDim.x) {
            const int r = e >> 9, col = e & 511;
            const int m = m0 + r;
            float acc = 0.f;
            for (int k = 0; k < KI; ++k)
                acc += __bfloat162float(g_hh[(size_t)m * KI + k])
                     * __bfloat162float(g_wd[(size_t)(n0 + col) * KI + k]);
            out[(size_t)m * KD + n0 + col] = acc * dsc;
        }
    }
}
#endif

// ---------------- launch ------------------------------------------------------
extern "C" void kernel_launch(void* const* d_in, const int* in_sizes, int n_in,
                              void* d_out, int out_size)
{
    const float* x  = (const float*)d_in[0];
    const int*   gw = (const int*)  d_in[1];
    const float* gs = (const float*)d_in[2];
    const int*   uw = (const int*)  d_in[3];
    const float* us = (const float*)d_in[4];
    const int*   dw = (const int*)  d_in[5];
    const float* ds = (const float*)d_in[6];
    float* out = (float*)d_out;

    cudaFuncSetAttribute(kmain, cudaFuncAttributeMaxDynamicSharedMemorySize, GSMEM);

    prep<<<PREP_NB, 256>>>(gw, uw, dw, x);
    kmain<<<dim3(2, NPAIR, 1), NTHR, GSMEM>>>(gs, us, ds, out);
}